// round 1
// baseline (speedup 1.0000x reference)
#include <cuda_runtime.h>
#include <math.h>

// Problem constants
#define EMB   1024
#define HID   4096
#define BATCH 2
#define SEQT  4096
#define MROWS (BATCH * SEQT)   // 8192
#define EPS_F 1e-6f

// ---------------------------------------------------------------------------
// Scratch (static __device__ arrays; runtime allocation is forbidden)
// ---------------------------------------------------------------------------
__device__ float g_r[(size_t)MROWS * EMB];   //  32 MB : rmsnorm(x)
__device__ float g_a[(size_t)MROWS * HID];   // 128 MB : fc1 preact
__device__ float g_b[(size_t)MROWS * HID];   // 128 MB : fc2 preact (reused for rmsnorm(y))
__device__ float g_y[(size_t)MROWS * HID];   // 128 MB : bar output

// ---------------------------------------------------------------------------
// Block-wide sum reduce (valid result on thread 0)
// ---------------------------------------------------------------------------
__device__ __forceinline__ float block_reduce_sum(float v) {
    __shared__ float sh[32];
    int lane = threadIdx.x & 31;
    int wid  = threadIdx.x >> 5;
#pragma unroll
    for (int o = 16; o; o >>= 1) v += __shfl_xor_sync(0xffffffffu, v, o);
    if (lane == 0) sh[wid] = v;
    __syncthreads();
    int nw = blockDim.x >> 5;
    if (wid == 0) {
        v = (lane < nw) ? sh[lane] : 0.0f;
#pragma unroll
        for (int o = 16; o; o >>= 1) v += __shfl_xor_sync(0xffffffffu, v, o);
    }
    return v;
}

// ---------------------------------------------------------------------------
// Row-wise RMSNorm: out[row] = in[row] * rsqrt(mean(in[row]^2) + eps)
// One block (256 threads) per row. W must be a multiple of 1024.
// ---------------------------------------------------------------------------
__global__ void rmsnorm_kernel(const float* __restrict__ in,
                               float* __restrict__ outp, int W) {
    int row = blockIdx.x;
    const float4* ir = (const float4*)(in   + (size_t)row * W);
    float4*       orr = (float4*)(outp + (size_t)row * W);
    int nvec = W >> 2;            // float4s per row
    float ss = 0.0f;
    for (int i = threadIdx.x; i < nvec; i += 256) {
        float4 v = ir[i];
        ss += v.x * v.x + v.y * v.y + v.z * v.z + v.w * v.w;
    }
    ss = block_reduce_sum(ss);
    __shared__ float s_scale;
    if (threadIdx.x == 0) s_scale = rsqrtf(ss / (float)W + EPS_F);
    __syncthreads();
    float sc = s_scale;
    for (int i = threadIdx.x; i < nvec; i += 256) {
        float4 v = ir[i];
        v.x *= sc; v.y *= sc; v.z *= sc; v.w *= sc;
        orr[i] = v;
    }
}

// ---------------------------------------------------------------------------
// SIMT fp32 GEMM:  C[m,n] = sum_k A[m,k] * B[n,k]  (+ Cadd[m,n] if non-null)
// A: [M,K] row-major, B: [N,K] row-major (both K-major -> NT gemm).
// BM=BN=128, BK=16, 256 threads, 8x8 microtile.
// M % 128 == 0, N % 128 == 0, K % 16 == 0 assumed (true here).
// ---------------------------------------------------------------------------
__global__ void __launch_bounds__(256, 2)
gemm_nt_kernel(const float* __restrict__ A, const float* __restrict__ B,
               float* __restrict__ C, const float* __restrict__ Cadd,
               int M, int N, int K) {
    __shared__ float As[16][128];
    __shared__ float Bs[16][128];

    int tid = threadIdx.x;
    int bm = blockIdx.y * 128;
    int bn = blockIdx.x * 128;
    int tx = tid & 15;          // 0..15  (n dir)
    int ty = tid >> 4;          // 0..15  (m dir)

    int lr = tid >> 2;          // 0..63  tile row for loads
    int lc = (tid & 3) * 4;     // 0,4,8,12  k-offset for loads

    const float* Ab = A + (size_t)bm * K;
    const float* Bb = B + (size_t)bn * K;

    float acc[8][8];
#pragma unroll
    for (int i = 0; i < 8; i++)
#pragma unroll
        for (int j = 0; j < 8; j++) acc[i][j] = 0.0f;

    for (int k0 = 0; k0 < K; k0 += 16) {
#pragma unroll
        for (int half = 0; half < 2; half++) {
            int r = lr + half * 64;
            float4 va = *(const float4*)(Ab + (size_t)r * K + k0 + lc);
            As[lc + 0][r] = va.x; As[lc + 1][r] = va.y;
            As[lc + 2][r] = va.z; As[lc + 3][r] = va.w;
            float4 vb = *(const float4*)(Bb + (size_t)r * K + k0 + lc);
            Bs[lc + 0][r] = vb.x; Bs[lc + 1][r] = vb.y;
            Bs[lc + 2][r] = vb.z; Bs[lc + 3][r] = vb.w;
        }
        __syncthreads();

#pragma unroll
        for (int k = 0; k < 16; k++) {
            float ar[8], br[8];
            *(float4*)(ar)     = *(const float4*)&As[k][ty * 8];
            *(float4*)(ar + 4) = *(const float4*)&As[k][ty * 8 + 4];
            *(float4*)(br)     = *(const float4*)&Bs[k][tx * 8];
            *(float4*)(br + 4) = *(const float4*)&Bs[k][tx * 8 + 4];
#pragma unroll
            for (int i = 0; i < 8; i++)
#pragma unroll
                for (int j = 0; j < 8; j++)
                    acc[i][j] = fmaf(ar[i], br[j], acc[i][j]);
        }
        __syncthreads();
    }

    // epilogue
#pragma unroll
    for (int i = 0; i < 8; i++) {
        int row = bm + ty * 8 + i;
        float*       Cr = C + (size_t)row * N + bn + tx * 8;
        const float* Rr = Cadd ? (Cadd + (size_t)row * N + bn + tx * 8) : nullptr;
#pragma unroll
        for (int j = 0; j < 8; j += 4) {
            float4 v = make_float4(acc[i][j], acc[i][j + 1], acc[i][j + 2], acc[i][j + 3]);
            if (Rr) {
                float4 c0 = *(const float4*)(Rr + j);
                v.x += c0.x; v.y += c0.y; v.z += c0.z; v.w += c0.w;
            }
            *(float4*)(Cr + j) = v;
        }
    }
}

// ---------------------------------------------------------------------------
// Causal bar scan: per (batch, channel) running logsumexp of a and b,
//   y[t] = exp(la_t + lb_t - 2*log(t+1)) = sa*sb*exp(ma+mb)/(t+1)^2
// One thread per (b,h). Loads are coalesced across the h dimension.
// ---------------------------------------------------------------------------
__global__ void bar_scan_kernel(const float* __restrict__ a,
                                const float* __restrict__ b,
                                float* __restrict__ y) {
    int idx = blockIdx.x * blockDim.x + threadIdx.x;   // 0 .. BATCH*HID-1
    int bb = idx >> 12;           // / HID (4096)
    int h  = idx & (HID - 1);
    size_t base = (size_t)bb * SEQT * HID + h;
    const float* ap = a + base;
    const float* bp = b + base;
    float*       yp = y + base;

    float ma = -INFINITY, sa = 0.0f;
    float mb = -INFINITY, sb = 0.0f;
    for (int t = 0; t < SEQT; t++) {
        float av = ap[(size_t)t * HID];
        float bv = bp[(size_t)t * HID];

        float ma2 = fmaxf(ma, av);
        sa = sa * __expf(ma - ma2) + __expf(av - ma2);
        ma = ma2;

        float mb2 = fmaxf(mb, bv);
        sb = sb * __expf(mb - mb2) + __expf(bv - mb2);
        mb = mb2;

        float tt = (float)(t + 1);
        yp[(size_t)t * HID] = sa * sb * __expf(ma + mb) / (tt * tt);
    }
}

// ---------------------------------------------------------------------------
// kernel_launch
// Inputs (metadata order): x [B,T,EMB] f32, W1 [HID,EMB] f32,
//                          W2 [HID,EMB] f32, W3 [EMB,HID] f32
// Output: [B,T,EMB] f32
// ---------------------------------------------------------------------------
extern "C" void kernel_launch(void* const* d_in, const int* in_sizes, int n_in,
                              void* d_out, int out_size) {
    const float* x  = (const float*)d_in[0];
    const float* W1 = (const float*)d_in[1];
    const float* W2 = (const float*)d_in[2];
    const float* W3 = (const float*)d_in[3];
    float* out = (float*)d_out;

    float *r_p, *a_p, *b_p, *y_p;
    cudaGetSymbolAddress((void**)&r_p, g_r);
    cudaGetSymbolAddress((void**)&a_p, g_a);
    cudaGetSymbolAddress((void**)&b_p, g_b);
    cudaGetSymbolAddress((void**)&y_p, g_y);

    // 1) r = rmsnorm(x)                       [8192,1024]
    rmsnorm_kernel<<<MROWS, 256>>>(x, r_p, EMB);

    // 2) a = r @ W1^T ; b = r @ W2^T          [8192,4096]
    gemm_nt_kernel<<<dim3(HID / 128, MROWS / 128), 256>>>(r_p, W1, a_p, nullptr,
                                                          MROWS, HID, EMB);
    gemm_nt_kernel<<<dim3(HID / 128, MROWS / 128), 256>>>(r_p, W2, b_p, nullptr,
                                                          MROWS, HID, EMB);

    // 3) y = bar(a, b)  (causal quadratic scan)
    bar_scan_kernel<<<(BATCH * HID) / 256, 256>>>(a_p, b_p, y_p);

    // 4) yn = rmsnorm(y)  (reuse g_b as output buffer)
    rmsnorm_kernel<<<MROWS, 256>>>(y_p, b_p, HID);

    // 5) out = x + yn @ W3^T                  [8192,1024]
    gemm_nt_kernel<<<dim3(EMB / 128, MROWS / 128), 256>>>(b_p, W3, out, x,
                                                          MROWS, EMB, HID);
}

// round 3
// speedup vs baseline: 1.7611x; 1.7611x over previous
#include <cuda_runtime.h>
#include <cuda_bf16.h>
#include <cstdint>
#include <math.h>

// ---------------------------------------------------------------------------
// Problem constants
// ---------------------------------------------------------------------------
#define EMB   1024
#define HID   4096
#define BATCH 2
#define SEQT  4096
#define MROWS (BATCH * SEQT)   // 8192
#define EPS_F 1e-6f

// ---------------------------------------------------------------------------
// Scratch buffers (static; runtime allocation forbidden)
//   Packed operands use K' = 3K layout:
//     activations A' = [Ah | Al | Ah]  (hi at k and 2K+k, lo at K+k)
//     weights     B' = [Bh | Bh | Bl]  (hi at k and K+k,  lo at 2K+k)
//   so A'.B' = Ah*Bh + Al*Bh + Ah*Bl  (drops only the ~2^-18 lo*lo term)
// ---------------------------------------------------------------------------
__device__ __align__(16) __nv_bfloat16 g_ap [(size_t)MROWS * 3 * EMB];        //  50 MB
__device__ __align__(16) __nv_bfloat16 g_bp [(size_t)(2 * HID) * 3 * EMB];    // 100 MB (W1 stacked on W2)
__device__ __align__(16) __nv_bfloat16 g_w3p[(size_t)EMB * 3 * HID];          //  25 MB
__device__ __align__(16) __nv_bfloat16 g_ynp[(size_t)MROWS * 3 * HID];        // 201 MB
__device__ __align__(16) float g_a[(size_t)MROWS * HID];                      // 128 MB
__device__ __align__(16) float g_b[(size_t)MROWS * HID];                      // 128 MB
__device__ __align__(16) float g_y[(size_t)MROWS * HID];                      // 128 MB

// ---------------------------------------------------------------------------
// PTX helpers (all plain sm_103-legal: cp.async, ldmatrix, mma.sync)
// ---------------------------------------------------------------------------
__device__ __forceinline__ uint32_t smem_u32(const void* p) {
    uint32_t a;
    asm("{ .reg .u64 t; cvta.to.shared.u64 t, %1; cvt.u32.u64 %0, t; }"
        : "=r"(a) : "l"(p));
    return a;
}
__device__ __forceinline__ void cp16(uint32_t s, const void* g) {
    asm volatile("cp.async.cg.shared.global [%0], [%1], 16;" :: "r"(s), "l"(g));
}
__device__ __forceinline__ void cp_commit() {
    asm volatile("cp.async.commit_group;" ::: "memory");
}
__device__ __forceinline__ void ldsm_x4(uint32_t& r0, uint32_t& r1,
                                        uint32_t& r2, uint32_t& r3, uint32_t addr) {
    asm volatile("ldmatrix.sync.aligned.m8n8.x4.shared.b16 {%0,%1,%2,%3}, [%4];"
                 : "=r"(r0), "=r"(r1), "=r"(r2), "=r"(r3) : "r"(addr));
}
__device__ __forceinline__ void mma_bf16(float& d0, float& d1, float& d2, float& d3,
                                         uint32_t a0, uint32_t a1, uint32_t a2, uint32_t a3,
                                         uint32_t b0, uint32_t b1) {
    asm volatile(
        "mma.sync.aligned.m16n8k16.row.col.f32.bf16.bf16.f32 "
        "{%0,%1,%2,%3}, {%4,%5,%6,%7}, {%8,%9}, {%0,%1,%2,%3};"
        : "+f"(d0), "+f"(d1), "+f"(d2), "+f"(d3)
        : "r"(a0), "r"(a1), "r"(a2), "r"(a3), "r"(b0), "r"(b1));
}

// ---------------------------------------------------------------------------
// bf16 NT GEMM (HMMA): C[m,n] = sum_k A[m,k]*B[n,k]  (+ Cadd on C0 region)
// A: [M,K] bf16 K-major; B: [N,K] bf16 K-major.
// Column blocks with bn <  nsplit  -> C0 [M, nsplit]
//                    bn >= nsplit  -> C1 [M, N - nsplit]
// Tiles: 128x128x32, 3-stage cp.async pipeline, 256 threads (8 warps, 2x4).
// M%128==0, N%128==0, K%32==0, nsplit%128==0 required.
// ---------------------------------------------------------------------------
#define BM 128
#define BN 128
#define BK 32
#define STAGE_BYTES 16384          // A 8KB + B 8KB
#define NSTAGE 3
#define GEMM_SMEM (NSTAGE * STAGE_BYTES)

__device__ __forceinline__ void issue_tile_loads(
    uint32_t sbase, int st, const __nv_bfloat16* Ab, const __nv_bfloat16* Bb,
    int koff, int K, int tid)
{
    uint32_t stage = sbase + (uint32_t)st * STAGE_BYTES;
#pragma unroll
    for (int t = 0; t < 2; t++) {
        int idx = tid + t * 256;              // 0..511
        int row = idx >> 2;                   // 0..127
        int u   = idx & 3;                    // 16B unit within 64B row
        uint32_t sw = (uint32_t)(u ^ ((row >> 1) & 3)) << 4;
        cp16(stage        + row * 64 + sw, Ab + (size_t)row * K + koff + u * 8);
        cp16(stage + 8192 + row * 64 + sw, Bb + (size_t)row * K + koff + u * 8);
    }
}

__global__ void __launch_bounds__(256, 2)
hgemm_kernel(const __nv_bfloat16* __restrict__ A, const __nv_bfloat16* __restrict__ B,
             float* __restrict__ C0, float* __restrict__ C1,
             const float* __restrict__ Cadd,
             int M, int N, int K, int nsplit)
{
    extern __shared__ char smem[];
    uint32_t sbase = smem_u32(smem);
    const int tid  = threadIdx.x;
    const int wid  = tid >> 5;
    const int lane = tid & 31;
    const int wm   = wid & 1;        // 2 warps in m
    const int wn   = wid >> 1;       // 4 warps in n
    const int bm   = blockIdx.y * BM;
    const int bn   = blockIdx.x * BN;
    const int NC   = K / BK;

    const __nv_bfloat16* Ab = A + (size_t)bm * K;
    const __nv_bfloat16* Bb = B + (size_t)bn * K;

    float acc[4][4][4];
#pragma unroll
    for (int i = 0; i < 4; i++)
#pragma unroll
        for (int j = 0; j < 4; j++)
#pragma unroll
            for (int q = 0; q < 4; q++) acc[i][j][q] = 0.0f;

    // precomputed ldmatrix lane addressing (within a stage)
    // A: m-row = wm*64 + mf*16 + (lane&15), k-unit = kstep*2 + (lane>>4)
    const int a_m   = wm * 64 + (lane & 15);
    const int a_ku  = lane >> 4;               // 0/1
    // B: n-row = wn*32 + nf2*16 + (lane&7) + ((lane>>4)<<3), k-unit = kstep*2 + ((lane>>3)&1)
    const int b_n   = wn * 32 + (lane & 7) + ((lane >> 4) << 3);
    const int b_ku  = (lane >> 3) & 1;

    // prologue
    issue_tile_loads(sbase, 0, Ab, Bb, 0,  K, tid); cp_commit();
    issue_tile_loads(sbase, 1, Ab, Bb, BK, K, tid); cp_commit();

    for (int c = 0; c < NC; c++) {
        if (c + 1 < NC) asm volatile("cp.async.wait_group 1;" ::: "memory");
        else            asm volatile("cp.async.wait_group 0;" ::: "memory");
        __syncthreads();

        if (c + 2 < NC) {
            issue_tile_loads(sbase, (c + 2) % NSTAGE, Ab, Bb, (c + 2) * BK, K, tid);
            cp_commit();
        }

        uint32_t stage = sbase + (uint32_t)(c % NSTAGE) * STAGE_BYTES;
#pragma unroll
        for (int ks = 0; ks < 2; ks++) {
            uint32_t a0[4], a1[4], a2[4], a3[4];
            uint32_t bb0[2], bb1[2], bb2[2], bb3[2];
#pragma unroll
            for (int mf = 0; mf < 4; mf++) {
                int m = a_m + mf * 16;
                int ku = ks * 2 + a_ku;
                uint32_t sw = (uint32_t)(ku ^ ((m >> 1) & 3)) << 4;
                ldsm_x4(a0[mf], a1[mf], a2[mf], a3[mf], stage + m * 64 + sw);
            }
#pragma unroll
            for (int nf2 = 0; nf2 < 2; nf2++) {
                int n = b_n + nf2 * 16;
                int ku = ks * 2 + b_ku;
                uint32_t sw = (uint32_t)(ku ^ ((n >> 1) & 3)) << 4;
                uint32_t r0, r1, r2, r3;
                ldsm_x4(r0, r1, r2, r3, stage + 8192 + n * 64 + sw);
                if (nf2 == 0) { bb0[0] = r0; bb0[1] = r1; bb1[0] = r2; bb1[1] = r3; }
                else          { bb2[0] = r0; bb2[1] = r1; bb3[0] = r2; bb3[1] = r3; }
            }
#pragma unroll
            for (int mf = 0; mf < 4; mf++) {
                mma_bf16(acc[mf][0][0], acc[mf][0][1], acc[mf][0][2], acc[mf][0][3],
                         a0[mf], a1[mf], a2[mf], a3[mf], bb0[0], bb0[1]);
                mma_bf16(acc[mf][1][0], acc[mf][1][1], acc[mf][1][2], acc[mf][1][3],
                         a0[mf], a1[mf], a2[mf], a3[mf], bb1[0], bb1[1]);
                mma_bf16(acc[mf][2][0], acc[mf][2][1], acc[mf][2][2], acc[mf][2][3],
                         a0[mf], a1[mf], a2[mf], a3[mf], bb2[0], bb2[1]);
                mma_bf16(acc[mf][3][0], acc[mf][3][1], acc[mf][3][2], acc[mf][3][3],
                         a0[mf], a1[mf], a2[mf], a3[mf], bb3[0], bb3[1]);
            }
        }
        __syncthreads();
    }

    // epilogue
    const int   inC0 = (bn < nsplit);
    float*      Cb   = inC0 ? C0 : C1;
    const int   ldc  = inC0 ? nsplit : (N - nsplit);
    const int   cb   = inC0 ? bn : bn - nsplit;

#pragma unroll
    for (int mf = 0; mf < 4; mf++) {
        int r0 = bm + wm * 64 + mf * 16 + (lane >> 2);
        int r1 = r0 + 8;
#pragma unroll
        for (int nf = 0; nf < 4; nf++) {
            int col = cb + wn * 32 + nf * 8 + (lane & 3) * 2;
            float2 v0 = make_float2(acc[mf][nf][0], acc[mf][nf][1]);
            float2 v1 = make_float2(acc[mf][nf][2], acc[mf][nf][3]);
            if (Cadd) {
                const float2 s0 = *(const float2*)(Cadd + (size_t)r0 * ldc + col);
                const float2 s1 = *(const float2*)(Cadd + (size_t)r1 * ldc + col);
                v0.x += s0.x; v0.y += s0.y;
                v1.x += s1.x; v1.y += s1.y;
            }
            *(float2*)(Cb + (size_t)r0 * ldc + col) = v0;
            *(float2*)(Cb + (size_t)r1 * ldc + col) = v1;
        }
    }
}

// ---------------------------------------------------------------------------
// Block-wide sum reduce
// ---------------------------------------------------------------------------
__device__ __forceinline__ float block_reduce_sum(float v) {
    __shared__ float sh[32];
    int lane = threadIdx.x & 31;
    int wid  = threadIdx.x >> 5;
#pragma unroll
    for (int o = 16; o; o >>= 1) v += __shfl_xor_sync(0xffffffffu, v, o);
    if (lane == 0) sh[wid] = v;
    __syncthreads();
    int nw = blockDim.x >> 5;
    if (wid == 0) {
        v = (lane < nw) ? sh[lane] : 0.0f;
#pragma unroll
        for (int o = 16; o; o >>= 1) v += __shfl_xor_sync(0xffffffffu, v, o);
    }
    return v;
}

// ---------------------------------------------------------------------------
// RMSNorm + pack to activation triple-K layout [h | l | h].
// One block (256 thr) per row; W multiple of 1024.
// ---------------------------------------------------------------------------
__global__ void rmsnorm_pack_kernel(const float* __restrict__ in,
                                    __nv_bfloat16* __restrict__ outp, int W) {
    int row = blockIdx.x;
    const float4* ir = (const float4*)(in + (size_t)row * W);
    int nvec = W >> 2;
    float ss = 0.0f;
    for (int i = threadIdx.x; i < nvec; i += 256) {
        float4 v = ir[i];
        ss += v.x * v.x + v.y * v.y + v.z * v.z + v.w * v.w;
    }
    ss = block_reduce_sum(ss);
    __shared__ float s_scale;
    if (threadIdx.x == 0) s_scale = rsqrtf(ss / (float)W + EPS_F);
    __syncthreads();
    float sc = s_scale;
    __nv_bfloat162* ob = (__nv_bfloat162*)(outp + (size_t)row * 3 * W);
    int Wh = W >> 1;   // bf162 units per K block
    for (int i = threadIdx.x; i < nvec; i += 256) {
        float4 v = ir[i];
        v.x *= sc; v.y *= sc; v.z *= sc; v.w *= sc;
        __nv_bfloat162 h0 = __floats2bfloat162_rn(v.x, v.y);
        __nv_bfloat162 h1 = __floats2bfloat162_rn(v.z, v.w);
        __nv_bfloat162 l0 = __floats2bfloat162_rn(v.x - __bfloat162float(h0.x),
                                                  v.y - __bfloat162float(h0.y));
        __nv_bfloat162 l1 = __floats2bfloat162_rn(v.z - __bfloat162float(h1.x),
                                                  v.w - __bfloat162float(h1.y));
        ob[2 * i]              = h0; ob[2 * i + 1]          = h1;  // Ah @ [0,K)
        ob[Wh + 2 * i]         = l0; ob[Wh + 2 * i + 1]     = l1;  // Al @ [K,2K)
        ob[2 * Wh + 2 * i]     = h0; ob[2 * Wh + 2 * i + 1] = h1;  // Ah @ [2K,3K)
    }
}

// ---------------------------------------------------------------------------
// Weight pack to triple-K layout [h | h | l].
// ---------------------------------------------------------------------------
__global__ void wpack_kernel(const float* __restrict__ in,
                             __nv_bfloat16* __restrict__ outp,
                             int W, int total_vec) {
    int i = blockIdx.x * blockDim.x + threadIdx.x;
    if (i >= total_vec) return;
    int wv  = W >> 2;            // float4s per row
    int row = i / wv;
    int kv  = i - row * wv;
    float4 v = ((const float4*)in)[i];
    __nv_bfloat162 h0 = __floats2bfloat162_rn(v.x, v.y);
    __nv_bfloat162 h1 = __floats2bfloat162_rn(v.z, v.w);
    __nv_bfloat162 l0 = __floats2bfloat162_rn(v.x - __bfloat162float(h0.x),
                                              v.y - __bfloat162float(h0.y));
    __nv_bfloat162 l1 = __floats2bfloat162_rn(v.z - __bfloat162float(h1.x),
                                              v.w - __bfloat162float(h1.y));
    __nv_bfloat162* ob = (__nv_bfloat162*)(outp + (size_t)row * 3 * W);
    int Wh = W >> 1;
    ob[2 * kv]              = h0; ob[2 * kv + 1]          = h1;  // Bh @ [0,K)
    ob[Wh + 2 * kv]         = h0; ob[Wh + 2 * kv + 1]     = h1;  // Bh @ [K,2K)
    ob[2 * Wh + 2 * kv]     = l0; ob[2 * Wh + 2 * kv + 1] = l1;  // Bl @ [2K,3K)
}

// ---------------------------------------------------------------------------
// Causal bar scan (per (batch, channel) running logsumexp)
// ---------------------------------------------------------------------------
__global__ void bar_scan_kernel(const float* __restrict__ a,
                                const float* __restrict__ b,
                                float* __restrict__ y) {
    int idx = blockIdx.x * blockDim.x + threadIdx.x;
    int bb = idx >> 12;
    int h  = idx & (HID - 1);
    size_t base = (size_t)bb * SEQT * HID + h;
    const float* ap = a + base;
    const float* bp = b + base;
    float*       yp = y + base;

    float ma = -INFINITY, sa = 0.0f;
    float mb = -INFINITY, sb = 0.0f;
    for (int t = 0; t < SEQT; t++) {
        float av = ap[(size_t)t * HID];
        float bv = bp[(size_t)t * HID];

        float ma2 = fmaxf(ma, av);
        sa = sa * __expf(ma - ma2) + __expf(av - ma2);
        ma = ma2;

        float mb2 = fmaxf(mb, bv);
        sb = sb * __expf(mb - mb2) + __expf(bv - mb2);
        mb = mb2;

        float tt = (float)(t + 1);
        yp[(size_t)t * HID] = sa * sb * __expf(ma + mb) / (tt * tt);
    }
}

// ---------------------------------------------------------------------------
// kernel_launch
// ---------------------------------------------------------------------------
extern "C" void kernel_launch(void* const* d_in, const int* in_sizes, int n_in,
                              void* d_out, int out_size) {
    const float* x  = (const float*)d_in[0];
    const float* W1 = (const float*)d_in[1];
    const float* W2 = (const float*)d_in[2];
    const float* W3 = (const float*)d_in[3];
    float* out = (float*)d_out;

    __nv_bfloat16 *ap, *bp, *w3p, *ynp;
    float *a_p, *b_p, *y_p;
    cudaGetSymbolAddress((void**)&ap,  g_ap);
    cudaGetSymbolAddress((void**)&bp,  g_bp);
    cudaGetSymbolAddress((void**)&w3p, g_w3p);
    cudaGetSymbolAddress((void**)&ynp, g_ynp);
    cudaGetSymbolAddress((void**)&a_p, g_a);
    cudaGetSymbolAddress((void**)&b_p, g_b);
    cudaGetSymbolAddress((void**)&y_p, g_y);

    cudaFuncSetAttribute(hgemm_kernel, cudaFuncAttributeMaxDynamicSharedMemorySize,
                         GEMM_SMEM);

    // Pack weights: W1 -> bp rows [0, HID), W2 -> bp rows [HID, 2*HID)
    {
        int nv = (HID * EMB) / 4;
        wpack_kernel<<<(nv + 255) / 256, 256>>>(W1, bp, EMB, nv);
        wpack_kernel<<<(nv + 255) / 256, 256>>>(W2, bp + (size_t)HID * 3 * EMB, EMB, nv);
        int nv3 = (EMB * HID) / 4;
        wpack_kernel<<<(nv3 + 255) / 256, 256>>>(W3, w3p, HID, nv3);
    }

    // 1) r = rmsnorm(x), packed triple-K  [8192, 3072]
    rmsnorm_pack_kernel<<<MROWS, 256>>>(x, ap, EMB);

    // 2) fused: [a | b] = r @ [W1; W2]^T    M=8192, N=8192, K'=3072
    hgemm_kernel<<<dim3((2 * HID) / BN, MROWS / BM), 256, GEMM_SMEM>>>(
        ap, bp, a_p, b_p, nullptr, MROWS, 2 * HID, 3 * EMB, HID);

    // 3) y = bar(a, b)
    bar_scan_kernel<<<(BATCH * HID) / 256, 256>>>(a_p, b_p, y_p);

    // 4) yn = rmsnorm(y), packed triple-K  [8192, 12288]
    rmsnorm_pack_kernel<<<MROWS, 256>>>(y_p, ynp, HID);

    // 5) out = x + yn @ W3^T   M=8192, N=1024, K'=12288
    hgemm_kernel<<<dim3(EMB / BN, MROWS / BM), 256, GEMM_SMEM>>>(
        ynp, w3p, out, out, x, MROWS, EMB, 3 * HID, EMB);
}

// round 4
// speedup vs baseline: 3.9908x; 2.2660x over previous
#include <cuda_runtime.h>
#include <cuda_bf16.h>
#include <cuda_fp16.h>
#include <cstdint>
#include <math.h>

// ---------------------------------------------------------------------------
// Problem constants
// ---------------------------------------------------------------------------
#define EMB   1024
#define HID   4096
#define BATCH 2
#define SEQT  4096
#define MROWS (BATCH * SEQT)   // 8192
#define EPS_F 1e-6f

// ---------------------------------------------------------------------------
// Scratch buffers (static; runtime allocation forbidden)
// GEMM1/2 use K' = 3K bf16 packing: A' = [Ah|Al|Ah], B' = [Bh|Bh|Bl]
//   => A'.B' = Ah*Bh + Al*Bh + Ah*Bl  (drops only ~2^-18 lo*lo term)
// GEMM3 uses plain fp16 (error damped by residual).
// ---------------------------------------------------------------------------
__device__ __align__(16) __nv_bfloat16 g_ap [(size_t)MROWS * 3 * EMB];       //  50 MB
__device__ __align__(16) __nv_bfloat16 g_bp [(size_t)(2 * HID) * 3 * EMB];   // 100 MB
__device__ __align__(16) __half        g_w3h[(size_t)EMB * HID];             //   8 MB
__device__ __align__(16) __half        g_ynh[(size_t)MROWS * HID];           //  67 MB
__device__ __align__(16) float g_a[(size_t)MROWS * HID];                     // 128 MB
__device__ __align__(16) float g_b[(size_t)MROWS * HID];                     // 128 MB
__device__ __align__(16) float g_y[(size_t)MROWS * HID];                     // 128 MB

// ---------------------------------------------------------------------------
// PTX helpers (plain sm_103-legal)
// ---------------------------------------------------------------------------
__device__ __forceinline__ uint32_t smem_u32(const void* p) {
    uint32_t a;
    asm("{ .reg .u64 t; cvta.to.shared.u64 t, %1; cvt.u32.u64 %0, t; }"
        : "=r"(a) : "l"(p));
    return a;
}
__device__ __forceinline__ void cp16(uint32_t s, const void* g) {
    asm volatile("cp.async.cg.shared.global [%0], [%1], 16;" :: "r"(s), "l"(g));
}
__device__ __forceinline__ void cp_commit() {
    asm volatile("cp.async.commit_group;" ::: "memory");
}
__device__ __forceinline__ void ldsm_x4(uint32_t& r0, uint32_t& r1,
                                        uint32_t& r2, uint32_t& r3, uint32_t addr) {
    asm volatile("ldmatrix.sync.aligned.m8n8.x4.shared.b16 {%0,%1,%2,%3}, [%4];"
                 : "=r"(r0), "=r"(r1), "=r"(r2), "=r"(r3) : "r"(addr));
}
template <int FP16>
__device__ __forceinline__ void mma16(float& d0, float& d1, float& d2, float& d3,
                                      uint32_t a0, uint32_t a1, uint32_t a2, uint32_t a3,
                                      uint32_t b0, uint32_t b1) {
    if (FP16)
        asm volatile(
            "mma.sync.aligned.m16n8k16.row.col.f32.f16.f16.f32 "
            "{%0,%1,%2,%3}, {%4,%5,%6,%7}, {%8,%9}, {%0,%1,%2,%3};"
            : "+f"(d0), "+f"(d1), "+f"(d2), "+f"(d3)
            : "r"(a0), "r"(a1), "r"(a2), "r"(a3), "r"(b0), "r"(b1));
    else
        asm volatile(
            "mma.sync.aligned.m16n8k16.row.col.f32.bf16.bf16.f32 "
            "{%0,%1,%2,%3}, {%4,%5,%6,%7}, {%8,%9}, {%0,%1,%2,%3};"
            : "+f"(d0), "+f"(d1), "+f"(d2), "+f"(d3)
            : "r"(a0), "r"(a1), "r"(a2), "r"(a3), "r"(b0), "r"(b1));
}

// ---------------------------------------------------------------------------
// 16-bit NT GEMM (HMMA): C[m,n] = sum_k A[m,k]*B[n,k] (+ Cadd on C0 region)
// Tiles: 128x128x64, 3-stage cp.async, 256 threads (8 warps 2x4), 2 CTA/SM.
// 128-byte smem rows with SW128 XOR swizzle.
// Column blocks: bn < nsplit -> C0 [M,nsplit], else C1 [M,N-nsplit].
// ---------------------------------------------------------------------------
#define BM 128
#define BN 128
#define BK 64
#define OPB 16384                  // bytes per operand tile (128 x 128B)
#define STAGE_BYTES (2 * OPB)      // A + B
#define NSTAGE 3
#define GEMM_SMEM (NSTAGE * STAGE_BYTES)

__device__ __forceinline__ uint32_t sw128(uint32_t off) {
    return off ^ ((off >> 3) & 0x70);
}

__device__ __forceinline__ void issue_tile_loads(
    uint32_t sbase, int st, const __nv_bfloat16* Ab, const __nv_bfloat16* Bb,
    int koff, int K, int tid)
{
    uint32_t stage = sbase + (uint32_t)st * STAGE_BYTES;
#pragma unroll
    for (int t = 0; t < 4; t++) {
        int idx = tid + t * 256;              // 0..1023
        int row = idx >> 3;                   // 0..127
        int u   = idx & 7;                    // 16B unit within 128B row
        uint32_t sw = sw128((uint32_t)idx << 4);
        cp16(stage       + sw, Ab + (size_t)row * K + koff + u * 8);
        cp16(stage + OPB + sw, Bb + (size_t)row * K + koff + u * 8);
    }
}

template <int FP16>
__global__ void __launch_bounds__(256, 2)
hgemm_kernel(const __nv_bfloat16* __restrict__ A, const __nv_bfloat16* __restrict__ B,
             float* __restrict__ C0, float* __restrict__ C1,
             const float* __restrict__ Cadd,
             int M, int N, int K, int nsplit)
{
    extern __shared__ char smem[];
    uint32_t sbase = smem_u32(smem);
    const int tid  = threadIdx.x;
    const int wid  = tid >> 5;
    const int lane = tid & 31;
    const int wm   = wid & 1;
    const int wn   = wid >> 1;
    const int bm   = blockIdx.y * BM;
    const int bn   = blockIdx.x * BN;
    const int NC   = K / BK;

    const __nv_bfloat16* Ab = A + (size_t)bm * K;
    const __nv_bfloat16* Bb = B + (size_t)bn * K;

    float acc[4][4][4];
#pragma unroll
    for (int i = 0; i < 4; i++)
#pragma unroll
        for (int j = 0; j < 4; j++)
#pragma unroll
            for (int q = 0; q < 4; q++) acc[i][j][q] = 0.0f;

    const int a_m  = wm * 64 + (lane & 15);
    const int a_ku = lane >> 4;               // 0/1
    const int b_n  = wn * 32 + (lane & 7) + ((lane >> 4) << 3);
    const int b_ku = (lane >> 3) & 1;

    issue_tile_loads(sbase, 0, Ab, Bb, 0,  K, tid); cp_commit();
    issue_tile_loads(sbase, 1, Ab, Bb, BK, K, tid); cp_commit();

    for (int c = 0; c < NC; c++) {
        if (c + 1 < NC) asm volatile("cp.async.wait_group 1;" ::: "memory");
        else            asm volatile("cp.async.wait_group 0;" ::: "memory");
        __syncthreads();

        if (c + 2 < NC) {
            issue_tile_loads(sbase, (c + 2) % NSTAGE, Ab, Bb, (c + 2) * BK, K, tid);
            cp_commit();
        }

        uint32_t stage = sbase + (uint32_t)(c % NSTAGE) * STAGE_BYTES;
#pragma unroll
        for (int ks = 0; ks < 4; ks++) {
            uint32_t a0[4], a1[4], a2[4], a3[4];
            uint32_t bb0[2], bb1[2], bb2[2], bb3[2];
#pragma unroll
            for (int mf = 0; mf < 4; mf++) {
                int m  = a_m + mf * 16;
                int ku = ks * 2 + a_ku;
                ldsm_x4(a0[mf], a1[mf], a2[mf], a3[mf],
                        stage + sw128((uint32_t)(m * 128 + ku * 16)));
            }
#pragma unroll
            for (int nf2 = 0; nf2 < 2; nf2++) {
                int n  = b_n + nf2 * 16;
                int ku = ks * 2 + b_ku;
                uint32_t r0, r1, r2, r3;
                ldsm_x4(r0, r1, r2, r3,
                        stage + OPB + sw128((uint32_t)(n * 128 + ku * 16)));
                if (nf2 == 0) { bb0[0] = r0; bb0[1] = r1; bb1[0] = r2; bb1[1] = r3; }
                else          { bb2[0] = r0; bb2[1] = r1; bb3[0] = r2; bb3[1] = r3; }
            }
#pragma unroll
            for (int mf = 0; mf < 4; mf++) {
                mma16<FP16>(acc[mf][0][0], acc[mf][0][1], acc[mf][0][2], acc[mf][0][3],
                            a0[mf], a1[mf], a2[mf], a3[mf], bb0[0], bb0[1]);
                mma16<FP16>(acc[mf][1][0], acc[mf][1][1], acc[mf][1][2], acc[mf][1][3],
                            a0[mf], a1[mf], a2[mf], a3[mf], bb1[0], bb1[1]);
                mma16<FP16>(acc[mf][2][0], acc[mf][2][1], acc[mf][2][2], acc[mf][2][3],
                            a0[mf], a1[mf], a2[mf], a3[mf], bb2[0], bb2[1]);
                mma16<FP16>(acc[mf][3][0], acc[mf][3][1], acc[mf][3][2], acc[mf][3][3],
                            a0[mf], a1[mf], a2[mf], a3[mf], bb3[0], bb3[1]);
            }
        }
        __syncthreads();
    }

    const int   inC0 = (bn < nsplit);
    float*      Cb   = inC0 ? C0 : C1;
    const int   ldc  = inC0 ? nsplit : (N - nsplit);
    const int   cb   = inC0 ? bn : bn - nsplit;

#pragma unroll
    for (int mf = 0; mf < 4; mf++) {
        int r0 = bm + wm * 64 + mf * 16 + (lane >> 2);
        int r1 = r0 + 8;
#pragma unroll
        for (int nf = 0; nf < 4; nf++) {
            int col = cb + wn * 32 + nf * 8 + (lane & 3) * 2;
            float2 v0 = make_float2(acc[mf][nf][0], acc[mf][nf][1]);
            float2 v1 = make_float2(acc[mf][nf][2], acc[mf][nf][3]);
            if (Cadd) {
                const float2 s0 = *(const float2*)(Cadd + (size_t)r0 * ldc + col);
                const float2 s1 = *(const float2*)(Cadd + (size_t)r1 * ldc + col);
                v0.x += s0.x; v0.y += s0.y;
                v1.x += s1.x; v1.y += s1.y;
            }
            *(float2*)(Cb + (size_t)r0 * ldc + col) = v0;
            *(float2*)(Cb + (size_t)r1 * ldc + col) = v1;
        }
    }
}

// ---------------------------------------------------------------------------
// Block-wide sum reduce
// ---------------------------------------------------------------------------
__device__ __forceinline__ float block_reduce_sum(float v) {
    __shared__ float sh[32];
    int lane = threadIdx.x & 31;
    int wid  = threadIdx.x >> 5;
#pragma unroll
    for (int o = 16; o; o >>= 1) v += __shfl_xor_sync(0xffffffffu, v, o);
    if (lane == 0) sh[wid] = v;
    __syncthreads();
    int nw = blockDim.x >> 5;
    if (wid == 0) {
        v = (lane < nw) ? sh[lane] : 0.0f;
#pragma unroll
        for (int o = 16; o; o >>= 1) v += __shfl_xor_sync(0xffffffffu, v, o);
    }
    return v;
}

// ---------------------------------------------------------------------------
// RMSNorm + pack to bf16 triple-K [h | l | h]. One block per row.
// ---------------------------------------------------------------------------
__global__ void rmsnorm_pack_kernel(const float* __restrict__ in,
                                    __nv_bfloat16* __restrict__ outp, int W) {
    int row = blockIdx.x;
    const float4* ir = (const float4*)(in + (size_t)row * W);
    int nvec = W >> 2;
    float ss = 0.0f;
    for (int i = threadIdx.x; i < nvec; i += 256) {
        float4 v = ir[i];
        ss += v.x * v.x + v.y * v.y + v.z * v.z + v.w * v.w;
    }
    ss = block_reduce_sum(ss);
    __shared__ float s_scale;
    if (threadIdx.x == 0) s_scale = rsqrtf(ss / (float)W + EPS_F);
    __syncthreads();
    float sc = s_scale;
    __nv_bfloat162* ob = (__nv_bfloat162*)(outp + (size_t)row * 3 * W);
    int Wh = W >> 1;
    for (int i = threadIdx.x; i < nvec; i += 256) {
        float4 v = ir[i];
        v.x *= sc; v.y *= sc; v.z *= sc; v.w *= sc;
        __nv_bfloat162 h0 = __floats2bfloat162_rn(v.x, v.y);
        __nv_bfloat162 h1 = __floats2bfloat162_rn(v.z, v.w);
        __nv_bfloat162 l0 = __floats2bfloat162_rn(v.x - __bfloat162float(h0.x),
                                                  v.y - __bfloat162float(h0.y));
        __nv_bfloat162 l1 = __floats2bfloat162_rn(v.z - __bfloat162float(h1.x),
                                                  v.w - __bfloat162float(h1.y));
        ob[2 * i]          = h0; ob[2 * i + 1]          = h1;
        ob[Wh + 2 * i]     = l0; ob[Wh + 2 * i + 1]     = l1;
        ob[2 * Wh + 2 * i] = h0; ob[2 * Wh + 2 * i + 1] = h1;
    }
}

// ---------------------------------------------------------------------------
// RMSNorm -> plain fp16. One block per row.
// ---------------------------------------------------------------------------
__global__ void rmsnorm_f16_kernel(const float* __restrict__ in,
                                   __half* __restrict__ outp, int W) {
    int row = blockIdx.x;
    const float4* ir = (const float4*)(in + (size_t)row * W);
    int nvec = W >> 2;
    float ss = 0.0f;
    for (int i = threadIdx.x; i < nvec; i += 256) {
        float4 v = ir[i];
        ss += v.x * v.x + v.y * v.y + v.z * v.z + v.w * v.w;
    }
    ss = block_reduce_sum(ss);
    __shared__ float s_scale;
    if (threadIdx.x == 0) s_scale = rsqrtf(ss / (float)W + EPS_F);
    __syncthreads();
    float sc = s_scale;
    __half2* op = (__half2*)(outp + (size_t)row * W);
    for (int i = threadIdx.x; i < nvec; i += 256) {
        float4 v = ir[i];
        op[2 * i]     = __floats2half2_rn(v.x * sc, v.y * sc);
        op[2 * i + 1] = __floats2half2_rn(v.z * sc, v.w * sc);
    }
}

// ---------------------------------------------------------------------------
// Weight packs
// ---------------------------------------------------------------------------
__global__ void wpack_kernel(const float* __restrict__ in,
                             __nv_bfloat16* __restrict__ outp,
                             int W, int total_vec) {
    int i = blockIdx.x * blockDim.x + threadIdx.x;
    if (i >= total_vec) return;
    int wv  = W >> 2;
    int row = i / wv;
    int kv  = i - row * wv;
    float4 v = ((const float4*)in)[i];
    __nv_bfloat162 h0 = __floats2bfloat162_rn(v.x, v.y);
    __nv_bfloat162 h1 = __floats2bfloat162_rn(v.z, v.w);
    __nv_bfloat162 l0 = __floats2bfloat162_rn(v.x - __bfloat162float(h0.x),
                                              v.y - __bfloat162float(h0.y));
    __nv_bfloat162 l1 = __floats2bfloat162_rn(v.z - __bfloat162float(h1.x),
                                              v.w - __bfloat162float(h1.y));
    __nv_bfloat162* ob = (__nv_bfloat162*)(outp + (size_t)row * 3 * W);
    int Wh = W >> 1;
    ob[2 * kv]          = h0; ob[2 * kv + 1]          = h1;
    ob[Wh + 2 * kv]     = h0; ob[Wh + 2 * kv + 1]     = h1;
    ob[2 * Wh + 2 * kv] = l0; ob[2 * Wh + 2 * kv + 1] = l1;
}

__global__ void wconv_f16_kernel(const float* __restrict__ in,
                                 __half* __restrict__ outp, int total_vec) {
    int i = blockIdx.x * blockDim.x + threadIdx.x;
    if (i >= total_vec) return;
    float4 v = ((const float4*)in)[i];
    ((__half2*)outp)[2 * i]     = __floats2half2_rn(v.x, v.y);
    ((__half2*)outp)[2 * i + 1] = __floats2half2_rn(v.z, v.w);
}

// ---------------------------------------------------------------------------
// Causal bar scan, UNSTABILIZED (values bounded ~exp(4)):
//   sa_t = sum_{i<=t} exp(a_i);  y'_t = sa_t * sb_t   (the 1/t^2 factor is a
//   per-(b,t) constant scale and cancels in the following rmsnorm).
// One thread per (batch, channel); 64-thread blocks spread across SMs.
// ---------------------------------------------------------------------------
__global__ void bar_scan_kernel(const float* __restrict__ a,
                                const float* __restrict__ b,
                                float* __restrict__ y) {
    int idx = blockIdx.x * 64 + threadIdx.x;
    int bb = idx >> 12;
    int h  = idx & (HID - 1);
    size_t base = (size_t)bb * SEQT * HID + h;
    const float* ap = a + base;
    const float* bp = b + base;
    float*       yp = y + base;

    float sa = 0.0f, sb = 0.0f;
#pragma unroll 4
    for (int t = 0; t < SEQT; t++) {
        sa += __expf(ap[(size_t)t * HID]);
        sb += __expf(bp[(size_t)t * HID]);
        yp[(size_t)t * HID] = sa * sb;
    }
}

// ---------------------------------------------------------------------------
// kernel_launch
// ---------------------------------------------------------------------------
extern "C" void kernel_launch(void* const* d_in, const int* in_sizes, int n_in,
                              void* d_out, int out_size) {
    const float* x  = (const float*)d_in[0];
    const float* W1 = (const float*)d_in[1];
    const float* W2 = (const float*)d_in[2];
    const float* W3 = (const float*)d_in[3];
    float* out = (float*)d_out;

    __nv_bfloat16 *ap, *bp;
    __half *w3h, *ynh;
    float *a_p, *b_p, *y_p;
    cudaGetSymbolAddress((void**)&ap,  g_ap);
    cudaGetSymbolAddress((void**)&bp,  g_bp);
    cudaGetSymbolAddress((void**)&w3h, g_w3h);
    cudaGetSymbolAddress((void**)&ynh, g_ynh);
    cudaGetSymbolAddress((void**)&a_p, g_a);
    cudaGetSymbolAddress((void**)&b_p, g_b);
    cudaGetSymbolAddress((void**)&y_p, g_y);

    cudaFuncSetAttribute(hgemm_kernel<0>, cudaFuncAttributeMaxDynamicSharedMemorySize,
                         GEMM_SMEM);
    cudaFuncSetAttribute(hgemm_kernel<1>, cudaFuncAttributeMaxDynamicSharedMemorySize,
                         GEMM_SMEM);

    // Pack weights
    {
        int nv = (HID * EMB) / 4;
        wpack_kernel<<<(nv + 255) / 256, 256>>>(W1, bp, EMB, nv);
        wpack_kernel<<<(nv + 255) / 256, 256>>>(W2, bp + (size_t)HID * 3 * EMB, EMB, nv);
        int nv3 = (EMB * HID) / 4;
        wconv_f16_kernel<<<(nv3 + 255) / 256, 256>>>(W3, w3h, nv3);
    }

    // 1) r = rmsnorm(x), packed triple-K  [8192, 3072]
    rmsnorm_pack_kernel<<<MROWS, 256>>>(x, ap, EMB);

    // 2) fused: [a | b] = r @ [W1; W2]^T    M=8192, N=8192, K'=3072
    hgemm_kernel<0><<<dim3((2 * HID) / BN, MROWS / BM), 256, GEMM_SMEM>>>(
        ap, bp, a_p, b_p, nullptr, MROWS, 2 * HID, 3 * EMB, HID);

    // 3) y' = bar(a, b) (unnormalized; t^2 cancels in rmsnorm)
    bar_scan_kernel<<<(BATCH * HID) / 64, 64>>>(a_p, b_p, y_p);

    // 4) yn = rmsnorm(y') -> fp16  [8192, 4096]
    rmsnorm_f16_kernel<<<MROWS, 256>>>(y_p, ynh, HID);

    // 5) out = x + yn @ W3^T   M=8192, N=1024, K=4096  (fp16 HMMA)
    hgemm_kernel<1><<<dim3(EMB / BN, MROWS / BM), 256, GEMM_SMEM>>>(
        (const __nv_bfloat16*)ynh, (const __nv_bfloat16*)w3h, out, out, x,
        MROWS, EMB, HID, EMB);
}

// round 6
// speedup vs baseline: 5.7017x; 1.4287x over previous
#include <cuda_runtime.h>
#include <cuda_bf16.h>
#include <cuda_fp16.h>
#include <cstdint>
#include <math.h>

// ---------------------------------------------------------------------------
// Problem constants
// ---------------------------------------------------------------------------
#define EMB   1024
#define HID   4096
#define BATCH 2
#define SEQT  4096
#define MROWS (BATCH * SEQT)   // 8192
#define EPS_F 1e-6f

// ---------------------------------------------------------------------------
// Scratch buffers (static; runtime allocation forbidden). All GEMMs fp16.
// ---------------------------------------------------------------------------
__device__ __align__(16) __half g_rh  [(size_t)MROWS * EMB];        //  16 MB
__device__ __align__(16) __half g_w12h[(size_t)(2 * HID) * EMB];    //  16 MB
__device__ __align__(16) __half g_w3h [(size_t)EMB * HID];          //   8 MB
__device__ __align__(16) __half g_ynh [(size_t)MROWS * HID];        //  67 MB
__device__ __align__(16) float g_a[(size_t)MROWS * HID];            // 128 MB
__device__ __align__(16) float g_b[(size_t)MROWS * HID];            // 128 MB
__device__ __align__(16) float g_y[(size_t)MROWS * HID];            // 128 MB

// ---------------------------------------------------------------------------
// PTX helpers (plain sm_103-legal)
// ---------------------------------------------------------------------------
__device__ __forceinline__ uint32_t smem_u32(const void* p) {
    uint32_t a;
    asm("{ .reg .u64 t; cvta.to.shared.u64 t, %1; cvt.u32.u64 %0, t; }"
        : "=r"(a) : "l"(p));
    return a;
}
__device__ __forceinline__ void cp16(uint32_t s, const void* g) {
    asm volatile("cp.async.cg.shared.global [%0], [%1], 16;" :: "r"(s), "l"(g));
}
__device__ __forceinline__ void cp_commit() {
    asm volatile("cp.async.commit_group;" ::: "memory");
}
__device__ __forceinline__ void ldsm_x4(uint32_t& r0, uint32_t& r1,
                                        uint32_t& r2, uint32_t& r3, uint32_t addr) {
    asm volatile("ldmatrix.sync.aligned.m8n8.x4.shared.b16 {%0,%1,%2,%3}, [%4];"
                 : "=r"(r0), "=r"(r1), "=r"(r2), "=r"(r3) : "r"(addr));
}
__device__ __forceinline__ void mma16(float& d0, float& d1, float& d2, float& d3,
                                      uint32_t a0, uint32_t a1, uint32_t a2, uint32_t a3,
                                      uint32_t b0, uint32_t b1) {
    asm volatile(
        "mma.sync.aligned.m16n8k16.row.col.f32.f16.f16.f32 "
        "{%0,%1,%2,%3}, {%4,%5,%6,%7}, {%8,%9}, {%0,%1,%2,%3};"
        : "+f"(d0), "+f"(d1), "+f"(d2), "+f"(d3)
        : "r"(a0), "r"(a1), "r"(a2), "r"(a3), "r"(b0), "r"(b1));
}

// ---------------------------------------------------------------------------
// fp16 NT GEMM (HMMA): C[m,n] = sum_k A[m,k]*B[n,k] (+ Cadd on C0 region)
// Tiles: 128x128x64, 3-stage cp.async, 256 threads (8 warps 2x4), 2 CTA/SM.
// 128-byte smem rows, SW128 XOR swizzle.
// Column blocks: bn < nsplit -> C0 [M,nsplit], else C1 [M,N-nsplit].
// ---------------------------------------------------------------------------
#define BM 128
#define BN 128
#define BK 64
#define OPB 16384
#define STAGE_BYTES (2 * OPB)
#define NSTAGE 3
#define GEMM_SMEM (NSTAGE * STAGE_BYTES)

__device__ __forceinline__ uint32_t sw128(uint32_t off) {
    return off ^ ((off >> 3) & 0x70);
}

__device__ __forceinline__ void issue_tile_loads(
    uint32_t sbase, int st, const __half* Ab, const __half* Bb,
    int koff, int K, int tid)
{
    uint32_t stage = sbase + (uint32_t)st * STAGE_BYTES;
#pragma unroll
    for (int t = 0; t < 4; t++) {
        int idx = tid + t * 256;              // 0..1023
        int row = idx >> 3;                   // 0..127
        int u   = idx & 7;                    // 16B unit within 128B row
        uint32_t sw = sw128((uint32_t)idx << 4);
        cp16(stage       + sw, Ab + (size_t)row * K + koff + u * 8);
        cp16(stage + OPB + sw, Bb + (size_t)row * K + koff + u * 8);
    }
}

__global__ void __launch_bounds__(256, 2)
hgemm_kernel(const __half* __restrict__ A, const __half* __restrict__ B,
             float* __restrict__ C0, float* __restrict__ C1,
             const float* __restrict__ Cadd,
             int M, int N, int K, int nsplit)
{
    extern __shared__ char smem[];
    uint32_t sbase = smem_u32(smem);
    const int tid  = threadIdx.x;
    const int wid  = tid >> 5;
    const int lane = tid & 31;
    const int wm   = wid & 1;
    const int wn   = wid >> 1;
    const int bm   = blockIdx.y * BM;
    const int bn   = blockIdx.x * BN;
    const int NC   = K / BK;

    const __half* Ab = A + (size_t)bm * K;
    const __half* Bb = B + (size_t)bn * K;

    float acc[4][4][4];
#pragma unroll
    for (int i = 0; i < 4; i++)
#pragma unroll
        for (int j = 0; j < 4; j++)
#pragma unroll
            for (int q = 0; q < 4; q++) acc[i][j][q] = 0.0f;

    const int a_m  = wm * 64 + (lane & 15);
    const int a_ku = lane >> 4;
    const int b_n  = wn * 32 + (lane & 7) + ((lane >> 4) << 3);
    const int b_ku = (lane >> 3) & 1;

    issue_tile_loads(sbase, 0, Ab, Bb, 0,  K, tid); cp_commit();
    issue_tile_loads(sbase, 1, Ab, Bb, BK, K, tid); cp_commit();

    for (int c = 0; c < NC; c++) {
        if (c + 1 < NC) asm volatile("cp.async.wait_group 1;" ::: "memory");
        else            asm volatile("cp.async.wait_group 0;" ::: "memory");
        __syncthreads();

        if (c + 2 < NC) {
            issue_tile_loads(sbase, (c + 2) % NSTAGE, Ab, Bb, (c + 2) * BK, K, tid);
            cp_commit();
        }

        uint32_t stage = sbase + (uint32_t)(c % NSTAGE) * STAGE_BYTES;
#pragma unroll
        for (int ks = 0; ks < 4; ks++) {
            uint32_t a0[4], a1[4], a2[4], a3[4];
            uint32_t bb0[2], bb1[2], bb2[2], bb3[2];
#pragma unroll
            for (int mf = 0; mf < 4; mf++) {
                int m  = a_m + mf * 16;
                int ku = ks * 2 + a_ku;
                ldsm_x4(a0[mf], a1[mf], a2[mf], a3[mf],
                        stage + sw128((uint32_t)(m * 128 + ku * 16)));
            }
#pragma unroll
            for (int nf2 = 0; nf2 < 2; nf2++) {
                int n  = b_n + nf2 * 16;
                int ku = ks * 2 + b_ku;
                uint32_t r0, r1, r2, r3;
                ldsm_x4(r0, r1, r2, r3,
                        stage + OPB + sw128((uint32_t)(n * 128 + ku * 16)));
                if (nf2 == 0) { bb0[0] = r0; bb0[1] = r1; bb1[0] = r2; bb1[1] = r3; }
                else          { bb2[0] = r0; bb2[1] = r1; bb3[0] = r2; bb3[1] = r3; }
            }
#pragma unroll
            for (int mf = 0; mf < 4; mf++) {
                mma16(acc[mf][0][0], acc[mf][0][1], acc[mf][0][2], acc[mf][0][3],
                      a0[mf], a1[mf], a2[mf], a3[mf], bb0[0], bb0[1]);
                mma16(acc[mf][1][0], acc[mf][1][1], acc[mf][1][2], acc[mf][1][3],
                      a0[mf], a1[mf], a2[mf], a3[mf], bb1[0], bb1[1]);
                mma16(acc[mf][2][0], acc[mf][2][1], acc[mf][2][2], acc[mf][2][3],
                      a0[mf], a1[mf], a2[mf], a3[mf], bb2[0], bb2[1]);
                mma16(acc[mf][3][0], acc[mf][3][1], acc[mf][3][2], acc[mf][3][3],
                      a0[mf], a1[mf], a2[mf], a3[mf], bb3[0], bb3[1]);
            }
        }
        __syncthreads();
    }

    const int   inC0 = (bn < nsplit);
    float*      Cb   = inC0 ? C0 : C1;
    const int   ldc  = inC0 ? nsplit : (N - nsplit);
    const int   cb   = inC0 ? bn : bn - nsplit;

#pragma unroll
    for (int mf = 0; mf < 4; mf++) {
        int r0 = bm + wm * 64 + mf * 16 + (lane >> 2);
        int r1 = r0 + 8;
#pragma unroll
        for (int nf = 0; nf < 4; nf++) {
            int col = cb + wn * 32 + nf * 8 + (lane & 3) * 2;
            float2 v0 = make_float2(acc[mf][nf][0], acc[mf][nf][1]);
            float2 v1 = make_float2(acc[mf][nf][2], acc[mf][nf][3]);
            if (Cadd) {
                const float2 s0 = *(const float2*)(Cadd + (size_t)r0 * ldc + col);
                const float2 s1 = *(const float2*)(Cadd + (size_t)r1 * ldc + col);
                v0.x += s0.x; v0.y += s0.y;
                v1.x += s1.x; v1.y += s1.y;
            }
            *(float2*)(Cb + (size_t)r0 * ldc + col) = v0;
            *(float2*)(Cb + (size_t)r1 * ldc + col) = v1;
        }
    }
}

// ---------------------------------------------------------------------------
// Block-wide sum reduce
// ---------------------------------------------------------------------------
__device__ __forceinline__ float block_reduce_sum(float v) {
    __shared__ float sh[32];
    int lane = threadIdx.x & 31;
    int wid  = threadIdx.x >> 5;
#pragma unroll
    for (int o = 16; o; o >>= 1) v += __shfl_xor_sync(0xffffffffu, v, o);
    if (lane == 0) sh[wid] = v;
    __syncthreads();
    int nw = blockDim.x >> 5;
    if (wid == 0) {
        v = (lane < nw) ? sh[lane] : 0.0f;
#pragma unroll
        for (int o = 16; o; o >>= 1) v += __shfl_xor_sync(0xffffffffu, v, o);
    }
    return v;
}

// ---------------------------------------------------------------------------
// RMSNorm -> fp16. One block (256 thr) per row; W multiple of 1024.
// ---------------------------------------------------------------------------
__global__ void rmsnorm_f16_kernel(const float* __restrict__ in,
                                   __half* __restrict__ outp, int W) {
    int row = blockIdx.x;
    const float4* ir = (const float4*)(in + (size_t)row * W);
    int nvec = W >> 2;
    float ss = 0.0f;
    for (int i = threadIdx.x; i < nvec; i += 256) {
        float4 v = ir[i];
        ss += v.x * v.x + v.y * v.y + v.z * v.z + v.w * v.w;
    }
    ss = block_reduce_sum(ss);
    __shared__ float s_scale;
    if (threadIdx.x == 0) s_scale = rsqrtf(ss / (float)W + EPS_F);
    __syncthreads();
    float sc = s_scale;
    __half2* op = (__half2*)(outp + (size_t)row * W);
    for (int i = threadIdx.x; i < nvec; i += 256) {
        float4 v = ir[i];
        op[2 * i]     = __floats2half2_rn(v.x * sc, v.y * sc);
        op[2 * i + 1] = __floats2half2_rn(v.z * sc, v.w * sc);
    }
}

// ---------------------------------------------------------------------------
// fp32 -> fp16 convert
// ---------------------------------------------------------------------------
__global__ void wconv_f16_kernel(const float* __restrict__ in,
                                 __half* __restrict__ outp, int total_vec) {
    int i = blockIdx.x * blockDim.x + threadIdx.x;
    if (i >= total_vec) return;
    float4 v = ((const float4*)in)[i];
    ((__half2*)outp)[2 * i]     = __floats2half2_rn(v.x, v.y);
    ((__half2*)outp)[2 * i + 1] = __floats2half2_rn(v.z, v.w);
}

// ---------------------------------------------------------------------------
// Causal bar scan, UNSTABILIZED (|preacts| small; fp32 range is ample):
//   sa_t = sum_{i<=t} exp(a_i);  y'_t = sa_t*sb_t  (1/t^2 cancels in rmsnorm)
// One thread per (batch, channel).
// ---------------------------------------------------------------------------
__global__ void bar_scan_kernel(const float* __restrict__ a,
                                const float* __restrict__ b,
                                float* __restrict__ y) {
    int idx = blockIdx.x * 64 + threadIdx.x;
    int bb = idx >> 12;
    int h  = idx & (HID - 1);
    size_t base = (size_t)bb * SEQT * HID + h;
    const float* ap = a + base;
    const float* bp = b + base;
    float*       yp = y + base;

    float sa = 0.0f, sb = 0.0f;
#pragma unroll 4
    for (int t = 0; t < SEQT; t++) {
        sa += __expf(ap[(size_t)t * HID]);
        sb += __expf(bp[(size_t)t * HID]);
        yp[(size_t)t * HID] = sa * sb;
    }
}

// ---------------------------------------------------------------------------
// kernel_launch
// ---------------------------------------------------------------------------
extern "C" void kernel_launch(void* const* d_in, const int* in_sizes, int n_in,
                              void* d_out, int out_size) {
    const float* x  = (const float*)d_in[0];
    const float* W1 = (const float*)d_in[1];
    const float* W2 = (const float*)d_in[2];
    const float* W3 = (const float*)d_in[3];
    float* out = (float*)d_out;

    __half *rh, *w12h, *w3h, *ynh;
    float *a_p, *b_p, *y_p;
    cudaGetSymbolAddress((void**)&rh,   g_rh);
    cudaGetSymbolAddress((void**)&w12h, g_w12h);
    cudaGetSymbolAddress((void**)&w3h,  g_w3h);
    cudaGetSymbolAddress((void**)&ynh,  g_ynh);
    cudaGetSymbolAddress((void**)&a_p,  g_a);
    cudaGetSymbolAddress((void**)&b_p,  g_b);
    cudaGetSymbolAddress((void**)&y_p,  g_y);

    cudaFuncSetAttribute(hgemm_kernel, cudaFuncAttributeMaxDynamicSharedMemorySize,
                         GEMM_SMEM);

    // Weight converts: W1 -> rows [0,HID), W2 -> rows [HID,2*HID)
    {
        int nv = (HID * EMB) / 4;
        wconv_f16_kernel<<<(nv + 255) / 256, 256>>>(W1, w12h, nv);
        wconv_f16_kernel<<<(nv + 255) / 256, 256>>>(W2, w12h + (size_t)HID * EMB, nv);
        int nv3 = (EMB * HID) / 4;
        wconv_f16_kernel<<<(nv3 + 255) / 256, 256>>>(W3, w3h, nv3);
    }

    // 1) r = rmsnorm(x) -> fp16  [8192, 1024]
    rmsnorm_f16_kernel<<<MROWS, 256>>>(x, rh, EMB);

    // 2) fused: [a | b] = r @ [W1; W2]^T    M=8192, N=8192, K=1024
    hgemm_kernel<<<dim3((2 * HID) / BN, MROWS / BM), 256, GEMM_SMEM>>>(
        rh, w12h, a_p, b_p, nullptr, MROWS, 2 * HID, EMB, HID);

    // 3) y' = bar(a, b) (unnormalized; t^2 cancels in rmsnorm)
    bar_scan_kernel<<<(BATCH * HID) / 64, 64>>>(a_p, b_p, y_p);

    // 4) yn = rmsnorm(y') -> fp16  [8192, 4096]
    rmsnorm_f16_kernel<<<MROWS, 256>>>(y_p, ynh, HID);

    // 5) out = x + yn @ W3^T   M=8192, N=1024, K=4096
    hgemm_kernel<<<dim3(EMB / BN, MROWS / BM), 256, GEMM_SMEM>>>(
        ynh, w3h, out, out, x, MROWS, EMB, HID, EMB);
}

// round 8
// speedup vs baseline: 6.6026x; 1.1580x over previous
#include <cuda_runtime.h>
#include <cuda_bf16.h>
#include <cuda_fp16.h>
#include <cstdint>
#include <math.h>

// ---------------------------------------------------------------------------
// Problem constants
// ---------------------------------------------------------------------------
#define EMB   1024
#define HID   4096
#define BATCH 2
#define SEQT  4096
#define MROWS (BATCH * SEQT)   // 8192
#define EPS_F 1e-6f

// ---------------------------------------------------------------------------
// Scratch buffers (static; runtime allocation forbidden). All GEMMs fp16.
// ---------------------------------------------------------------------------
__device__ __align__(16) __half g_rh  [(size_t)MROWS * EMB];        //  16 MB
__device__ __align__(16) __half g_w12h[(size_t)(2 * HID) * EMB];    //  16 MB
__device__ __align__(16) __half g_w3h [(size_t)EMB * HID];          //   8 MB
__device__ __align__(16) __half g_ynh [(size_t)MROWS * HID];        //  67 MB
__device__ __align__(16) float g_a[(size_t)MROWS * HID];            // 128 MB
__device__ __align__(16) float g_b[(size_t)MROWS * HID];            // 128 MB
__device__ __align__(16) float g_y[(size_t)MROWS * HID];            // 128 MB

// ---------------------------------------------------------------------------
// PTX helpers (plain sm_103-legal)
// ---------------------------------------------------------------------------
__device__ __forceinline__ uint32_t smem_u32(const void* p) {
    uint32_t a;
    asm("{ .reg .u64 t; cvta.to.shared.u64 t, %1; cvt.u32.u64 %0, t; }"
        : "=r"(a) : "l"(p));
    return a;
}
__device__ __forceinline__ void cp16(uint32_t s, const void* g) {
    asm volatile("cp.async.cg.shared.global [%0], [%1], 16;" :: "r"(s), "l"(g));
}
__device__ __forceinline__ void cp_commit() {
    asm volatile("cp.async.commit_group;" ::: "memory");
}
__device__ __forceinline__ void ldsm_x4(uint32_t& r0, uint32_t& r1,
                                        uint32_t& r2, uint32_t& r3, uint32_t addr) {
    asm volatile("ldmatrix.sync.aligned.m8n8.x4.shared.b16 {%0,%1,%2,%3}, [%4];"
                 : "=r"(r0), "=r"(r1), "=r"(r2), "=r"(r3) : "r"(addr));
}
__device__ __forceinline__ void mma16(float& d0, float& d1, float& d2, float& d3,
                                      uint32_t a0, uint32_t a1, uint32_t a2, uint32_t a3,
                                      uint32_t b0, uint32_t b1) {
    asm volatile(
        "mma.sync.aligned.m16n8k16.row.col.f32.f16.f16.f32 "
        "{%0,%1,%2,%3}, {%4,%5,%6,%7}, {%8,%9}, {%0,%1,%2,%3};"
        : "+f"(d0), "+f"(d1), "+f"(d2), "+f"(d3)
        : "r"(a0), "r"(a1), "r"(a2), "r"(a3), "r"(b0), "r"(b1));
}

// ---------------------------------------------------------------------------
// FMA-pipe exp (no MUFU): exp(x) = 2^n * e^r, n = round(x*log2e),
// r = x - n*ln2 in [-0.347, 0.347], degree-6 poly, 2^n via exponent add.
// Valid for |x| < 80 (preacts here are |x| <~ 5). Rel err ~1e-7.
// ---------------------------------------------------------------------------
__device__ __forceinline__ float exp_fma(float x) {
    const float MAGIC = 12582912.0f;  // 1.5 * 2^23
    float t = fmaf(x, 1.4426950408889634f, MAGIC);
    float n = t - MAGIC;
    float r = fmaf(n, -0.69314718055994531f, x);
    float p = 1.3888889e-3f;
    p = fmaf(p, r, 8.3333333e-3f);
    p = fmaf(p, r, 4.1666667e-2f);
    p = fmaf(p, r, 0.16666667f);
    p = fmaf(p, r, 0.5f);
    p = fmaf(p, r, 1.0f);
    p = fmaf(p, r, 1.0f);
    int ni = __float_as_int(t);
    return __int_as_float(__float_as_int(p) + (ni << 23));
}

// ---------------------------------------------------------------------------
// fp16 NT GEMM (HMMA): C[m,n] = sum_k A[m,k]*B[n,k] (+ Cadd on C0 region)
// Tiles: 128x128x64, 3-stage cp.async, 256 threads (8 warps 2x4), 2 CTA/SM.
// ---------------------------------------------------------------------------
#define BM 128
#define BN 128
#define BK 64
#define OPB 16384
#define STAGE_BYTES (2 * OPB)
#define NSTAGE 3
#define GEMM_SMEM (NSTAGE * STAGE_BYTES)

__device__ __forceinline__ uint32_t sw128(uint32_t off) {
    return off ^ ((off >> 3) & 0x70);
}

__device__ __forceinline__ void issue_tile_loads(
    uint32_t sbase, int st, const __half* Ab, const __half* Bb,
    int koff, int K, int tid)
{
    uint32_t stage = sbase + (uint32_t)st * STAGE_BYTES;
#pragma unroll
    for (int t = 0; t < 4; t++) {
        int idx = tid + t * 256;
        int row = idx >> 3;
        int u   = idx & 7;
        uint32_t sw = sw128((uint32_t)idx << 4);
        cp16(stage       + sw, Ab + (size_t)row * K + koff + u * 8);
        cp16(stage + OPB + sw, Bb + (size_t)row * K + koff + u * 8);
    }
}

__global__ void __launch_bounds__(256, 2)
hgemm_kernel(const __half* __restrict__ A, const __half* __restrict__ B,
             float* __restrict__ C0, float* __restrict__ C1,
             const float* __restrict__ Cadd,
             int M, int N, int K, int nsplit)
{
    extern __shared__ char smem[];
    uint32_t sbase = smem_u32(smem);
    const int tid  = threadIdx.x;
    const int wid  = tid >> 5;
    const int lane = tid & 31;
    const int wm   = wid & 1;
    const int wn   = wid >> 1;
    const int bm   = blockIdx.y * BM;
    const int bn   = blockIdx.x * BN;
    const int NC   = K / BK;

    const __half* Ab = A + (size_t)bm * K;
    const __half* Bb = B + (size_t)bn * K;

    float acc[4][4][4];
#pragma unroll
    for (int i = 0; i < 4; i++)
#pragma unroll
        for (int j = 0; j < 4; j++)
#pragma unroll
            for (int q = 0; q < 4; q++) acc[i][j][q] = 0.0f;

    const int a_m  = wm * 64 + (lane & 15);
    const int a_ku = lane >> 4;
    const int b_n  = wn * 32 + (lane & 7) + ((lane >> 4) << 3);
    const int b_ku = (lane >> 3) & 1;

    issue_tile_loads(sbase, 0, Ab, Bb, 0,  K, tid); cp_commit();
    issue_tile_loads(sbase, 1, Ab, Bb, BK, K, tid); cp_commit();

    for (int c = 0; c < NC; c++) {
        if (c + 1 < NC) asm volatile("cp.async.wait_group 1;" ::: "memory");
        else            asm volatile("cp.async.wait_group 0;" ::: "memory");
        __syncthreads();

        if (c + 2 < NC) {
            issue_tile_loads(sbase, (c + 2) % NSTAGE, Ab, Bb, (c + 2) * BK, K, tid);
            cp_commit();
        }

        uint32_t stage = sbase + (uint32_t)(c % NSTAGE) * STAGE_BYTES;
#pragma unroll
        for (int ks = 0; ks < 4; ks++) {
            uint32_t a0[4], a1[4], a2[4], a3[4];
            uint32_t bb0[2], bb1[2], bb2[2], bb3[2];
#pragma unroll
            for (int mf = 0; mf < 4; mf++) {
                int m  = a_m + mf * 16;
                int ku = ks * 2 + a_ku;
                ldsm_x4(a0[mf], a1[mf], a2[mf], a3[mf],
                        stage + sw128((uint32_t)(m * 128 + ku * 16)));
            }
#pragma unroll
            for (int nf2 = 0; nf2 < 2; nf2++) {
                int n  = b_n + nf2 * 16;
                int ku = ks * 2 + b_ku;
                uint32_t r0, r1, r2, r3;
                ldsm_x4(r0, r1, r2, r3,
                        stage + OPB + sw128((uint32_t)(n * 128 + ku * 16)));
                if (nf2 == 0) { bb0[0] = r0; bb0[1] = r1; bb1[0] = r2; bb1[1] = r3; }
                else          { bb2[0] = r0; bb2[1] = r1; bb3[0] = r2; bb3[1] = r3; }
            }
#pragma unroll
            for (int mf = 0; mf < 4; mf++) {
                mma16(acc[mf][0][0], acc[mf][0][1], acc[mf][0][2], acc[mf][0][3],
                      a0[mf], a1[mf], a2[mf], a3[mf], bb0[0], bb0[1]);
                mma16(acc[mf][1][0], acc[mf][1][1], acc[mf][1][2], acc[mf][1][3],
                      a0[mf], a1[mf], a2[mf], a3[mf], bb1[0], bb1[1]);
                mma16(acc[mf][2][0], acc[mf][2][1], acc[mf][2][2], acc[mf][2][3],
                      a0[mf], a1[mf], a2[mf], a3[mf], bb2[0], bb2[1]);
                mma16(acc[mf][3][0], acc[mf][3][1], acc[mf][3][2], acc[mf][3][3],
                      a0[mf], a1[mf], a2[mf], a3[mf], bb3[0], bb3[1]);
            }
        }
        __syncthreads();
    }

    const int   inC0 = (bn < nsplit);
    float*      Cb   = inC0 ? C0 : C1;
    const int   ldc  = inC0 ? nsplit : (N - nsplit);
    const int   cb   = inC0 ? bn : bn - nsplit;

#pragma unroll
    for (int mf = 0; mf < 4; mf++) {
        int r0 = bm + wm * 64 + mf * 16 + (lane >> 2);
        int r1 = r0 + 8;
#pragma unroll
        for (int nf = 0; nf < 4; nf++) {
            int col = cb + wn * 32 + nf * 8 + (lane & 3) * 2;
            float2 v0 = make_float2(acc[mf][nf][0], acc[mf][nf][1]);
            float2 v1 = make_float2(acc[mf][nf][2], acc[mf][nf][3]);
            if (Cadd) {
                const float2 s0 = *(const float2*)(Cadd + (size_t)r0 * ldc + col);
                const float2 s1 = *(const float2*)(Cadd + (size_t)r1 * ldc + col);
                v0.x += s0.x; v0.y += s0.y;
                v1.x += s1.x; v1.y += s1.y;
            }
            *(float2*)(Cb + (size_t)r0 * ldc + col) = v0;
            *(float2*)(Cb + (size_t)r1 * ldc + col) = v1;
        }
    }
}

// ---------------------------------------------------------------------------
// Block-wide sum reduce
// ---------------------------------------------------------------------------
__device__ __forceinline__ float block_reduce_sum(float v) {
    __shared__ float sh[32];
    int lane = threadIdx.x & 31;
    int wid  = threadIdx.x >> 5;
#pragma unroll
    for (int o = 16; o; o >>= 1) v += __shfl_xor_sync(0xffffffffu, v, o);
    if (lane == 0) sh[wid] = v;
    __syncthreads();
    int nw = blockDim.x >> 5;
    if (wid == 0) {
        v = (lane < nw) ? sh[lane] : 0.0f;
#pragma unroll
        for (int o = 16; o; o >>= 1) v += __shfl_xor_sync(0xffffffffu, v, o);
    }
    return v;
}

// ---------------------------------------------------------------------------
// RMSNorm -> fp16. One block (256 thr) per row; W multiple of 1024.
// ---------------------------------------------------------------------------
__global__ void rmsnorm_f16_kernel(const float* __restrict__ in,
                                   __half* __restrict__ outp, int W) {
    int row = blockIdx.x;
    const float4* ir = (const float4*)(in + (size_t)row * W);
    int nvec = W >> 2;
    float ss = 0.0f;
    for (int i = threadIdx.x; i < nvec; i += 256) {
        float4 v = ir[i];
        ss += v.x * v.x + v.y * v.y + v.z * v.z + v.w * v.w;
    }
    ss = block_reduce_sum(ss);
    __shared__ float s_scale;
    if (threadIdx.x == 0) s_scale = rsqrtf(ss / (float)W + EPS_F);
    __syncthreads();
    float sc = s_scale;
    __half2* op = (__half2*)(outp + (size_t)row * W);
    for (int i = threadIdx.x; i < nvec; i += 256) {
        float4 v = ir[i];
        op[2 * i]     = __floats2half2_rn(v.x * sc, v.y * sc);
        op[2 * i + 1] = __floats2half2_rn(v.z * sc, v.w * sc);
    }
}

// ---------------------------------------------------------------------------
// Fused fp32 -> fp16 convert for W1, W2, W3 in one launch.
// W1: nv12 float4s -> w12h[0..]; W2: nv12 -> w12h offset; W3: nv3 -> w3h.
// ---------------------------------------------------------------------------
__global__ void wconv_all_kernel(const float* __restrict__ W1,
                                 const float* __restrict__ W2,
                                 const float* __restrict__ W3,
                                 __half* __restrict__ w12h,
                                 __half* __restrict__ w3h,
                                 int nv12, int nv3) {
    int i = blockIdx.x * blockDim.x + threadIdx.x;
    const float* src;
    __half2* dst;
    int j;
    if (i < nv12)              { src = W1; dst = (__half2*)w12h;                j = i; }
    else if (i < 2 * nv12)     { src = W2; dst = (__half2*)(w12h + (size_t)nv12 * 4); j = i - nv12; }
    else if (i < 2 * nv12 + nv3) { src = W3; dst = (__half2*)w3h;              j = i - 2 * nv12; }
    else return;
    float4 v = ((const float4*)src)[j];
    dst[2 * j]     = __floats2half2_rn(v.x, v.y);
    dst[2 * j + 1] = __floats2half2_rn(v.z, v.w);
}

// ---------------------------------------------------------------------------
// Causal bar scan. FMA-pipe exp, unroll-16 batched loads for MLP.
//   sa_t = sum_{i<=t} exp(a_i);  y'_t = sa_t*sb_t  (1/t^2 cancels in rmsnorm)
// One thread per (batch, channel); 32-thread blocks, 256 blocks.
// ---------------------------------------------------------------------------
__global__ void bar_scan_kernel(const float* __restrict__ a,
                                const float* __restrict__ b,
                                float* __restrict__ y) {
    int idx = blockIdx.x * 32 + threadIdx.x;
    int bb = idx >> 12;
    int h  = idx & (HID - 1);
    size_t base = (size_t)bb * SEQT * HID + h;
    const float* ap = a + base;
    const float* bp = b + base;
    float*       yp = y + base;

    float sa = 0.0f, sb = 0.0f;
    for (int t0 = 0; t0 < SEQT; t0 += 16) {
        float av[16], bv[16];
#pragma unroll
        for (int i = 0; i < 16; i++) {
            av[i] = ap[(size_t)(t0 + i) * HID];
            bv[i] = bp[(size_t)(t0 + i) * HID];
        }
        float ea[16], eb[16];
#pragma unroll
        for (int i = 0; i < 16; i++) {
            ea[i] = exp_fma(av[i]);
            eb[i] = exp_fma(bv[i]);
        }
#pragma unroll
        for (int i = 0; i < 16; i++) {
            sa += ea[i];
            sb += eb[i];
            yp[(size_t)(t0 + i) * HID] = sa * sb;
        }
    }
}

// ---------------------------------------------------------------------------
// kernel_launch
// ---------------------------------------------------------------------------
extern "C" void kernel_launch(void* const* d_in, const int* in_sizes, int n_in,
                              void* d_out, int out_size) {
    const float* x  = (const float*)d_in[0];
    const float* W1 = (const float*)d_in[1];
    const float* W2 = (const float*)d_in[2];
    const float* W3 = (const float*)d_in[3];
    float* out = (float*)d_out;

    __half *rh, *w12h, *w3h, *ynh;
    float *a_p, *b_p, *y_p;
    cudaGetSymbolAddress((void**)&rh,   g_rh);
    cudaGetSymbolAddress((void**)&w12h, g_w12h);
    cudaGetSymbolAddress((void**)&w3h,  g_w3h);
    cudaGetSymbolAddress((void**)&ynh,  g_ynh);
    cudaGetSymbolAddress((void**)&a_p,  g_a);
    cudaGetSymbolAddress((void**)&b_p,  g_b);
    cudaGetSymbolAddress((void**)&y_p,  g_y);

    cudaFuncSetAttribute(hgemm_kernel, cudaFuncAttributeMaxDynamicSharedMemorySize,
                         GEMM_SMEM);

    // Weight converts, one launch
    {
        int nv12 = (HID * EMB) / 4;
        int nv3  = (EMB * HID) / 4;
        int tot  = 2 * nv12 + nv3;
        wconv_all_kernel<<<(tot + 255) / 256, 256>>>(W1, W2, W3, w12h, w3h, nv12, nv3);
    }

    // 1) r = rmsnorm(x) -> fp16  [8192, 1024]
    rmsnorm_f16_kernel<<<MROWS, 256>>>(x, rh, EMB);

    // 2) fused: [a | b] = r @ [W1; W2]^T    M=8192, N=8192, K=1024
    hgemm_kernel<<<dim3((2 * HID) / BN, MROWS / BM), 256, GEMM_SMEM>>>(
        rh, w12h, a_p, b_p, nullptr, MROWS, 2 * HID, EMB, HID);

    // 3) y' = bar(a, b) (unnormalized; t^2 cancels in rmsnorm)
    bar_scan_kernel<<<(BATCH * HID) / 32, 32>>>(a_p, b_p, y_p);

    // 4) yn = rmsnorm(y') -> fp16  [8192, 4096]
    rmsnorm_f16_kernel<<<MROWS, 256>>>(y_p, ynh, HID);

    // 5) out = x + yn @ W3^T   M=8192, N=1024, K=4096
    hgemm_kernel<<<dim3(EMB / BN, MROWS / BM), 256, GEMM_SMEM>>>(
        ynh, w3h, out, out, x, MROWS, EMB, HID, EMB);
}

// round 11
// speedup vs baseline: 10.6286x; 1.6098x over previous
#include <cuda_runtime.h>
#include <cuda_bf16.h>
#include <cuda_fp16.h>
#include <cstdint>
#include <math.h>

// ---------------------------------------------------------------------------
// Problem constants
// ---------------------------------------------------------------------------
#define EMB   1024
#define HID   4096
#define BATCH 2
#define SEQT  4096
#define MROWS (BATCH * SEQT)   // 8192
#define EPS_F 1e-6f
#define NCHUNK 32
#define CHUNK  (SEQT / NCHUNK)   // 128

// ---------------------------------------------------------------------------
// Scratch buffers (static; runtime allocation forbidden). All GEMMs fp16.
// ---------------------------------------------------------------------------
__device__ __align__(16) __half g_rh  [(size_t)MROWS * EMB];        //  16 MB
__device__ __align__(16) __half g_w12h[(size_t)(2 * HID) * EMB];    //  16 MB
__device__ __align__(16) __half g_w3h [(size_t)EMB * HID];          //   8 MB
__device__ __align__(16) __half g_ynh [(size_t)MROWS * HID];        //  67 MB
__device__ __align__(16) float g_a[(size_t)MROWS * HID];            // 128 MB
__device__ __align__(16) float g_b[(size_t)MROWS * HID];            // 128 MB
__device__ __align__(16) float g_y[(size_t)MROWS * HID];            // 128 MB
__device__ __align__(16) float g_pa[(size_t)BATCH * NCHUNK * HID];  //   1 MB
__device__ __align__(16) float g_pb[(size_t)BATCH * NCHUNK * HID];  //   1 MB

// ---------------------------------------------------------------------------
// PTX helpers (plain sm_103-legal)
// ---------------------------------------------------------------------------
__device__ __forceinline__ uint32_t smem_u32(const void* p) {
    uint32_t a;
    asm("{ .reg .u64 t; cvta.to.shared.u64 t, %1; cvt.u32.u64 %0, t; }"
        : "=r"(a) : "l"(p));
    return a;
}
__device__ __forceinline__ void cp16(uint32_t s, const void* g) {
    asm volatile("cp.async.cg.shared.global [%0], [%1], 16;" :: "r"(s), "l"(g));
}
__device__ __forceinline__ void cp_commit() {
    asm volatile("cp.async.commit_group;" ::: "memory");
}
__device__ __forceinline__ void ldsm_x4(uint32_t& r0, uint32_t& r1,
                                        uint32_t& r2, uint32_t& r3, uint32_t addr) {
    asm volatile("ldmatrix.sync.aligned.m8n8.x4.shared.b16 {%0,%1,%2,%3}, [%4];"
                 : "=r"(r0), "=r"(r1), "=r"(r2), "=r"(r3) : "r"(addr));
}
__device__ __forceinline__ void mma16(float& d0, float& d1, float& d2, float& d3,
                                      uint32_t a0, uint32_t a1, uint32_t a2, uint32_t a3,
                                      uint32_t b0, uint32_t b1) {
    asm volatile(
        "mma.sync.aligned.m16n8k16.row.col.f32.f16.f16.f32 "
        "{%0,%1,%2,%3}, {%4,%5,%6,%7}, {%8,%9}, {%0,%1,%2,%3};"
        : "+f"(d0), "+f"(d1), "+f"(d2), "+f"(d3)
        : "r"(a0), "r"(a1), "r"(a2), "r"(a3), "r"(b0), "r"(b1));
}

// ---------------------------------------------------------------------------
// fp16 NT GEMM (HMMA): C[m,n] = sum_k A[m,k]*B[n,k] (+ Cadd on C0 region)
// Tiles: 128x128x64, 3-stage cp.async, 256 threads (8 warps 2x4), 2 CTA/SM.
// ---------------------------------------------------------------------------
#define BM 128
#define BN 128
#define BK 64
#define OPB 16384
#define STAGE_BYTES (2 * OPB)
#define NSTAGE 3
#define GEMM_SMEM (NSTAGE * STAGE_BYTES)

__device__ __forceinline__ uint32_t sw128(uint32_t off) {
    return off ^ ((off >> 3) & 0x70);
}

__device__ __forceinline__ void issue_tile_loads(
    uint32_t sbase, int st, const __half* Ab, const __half* Bb,
    int koff, int K, int tid)
{
    uint32_t stage = sbase + (uint32_t)st * STAGE_BYTES;
#pragma unroll
    for (int t = 0; t < 4; t++) {
        int idx = tid + t * 256;
        int row = idx >> 3;
        int u   = idx & 7;
        uint32_t sw = sw128((uint32_t)idx << 4);
        cp16(stage       + sw, Ab + (size_t)row * K + koff + u * 8);
        cp16(stage + OPB + sw, Bb + (size_t)row * K + koff + u * 8);
    }
}

__global__ void __launch_bounds__(256, 2)
hgemm_kernel(const __half* __restrict__ A, const __half* __restrict__ B,
             float* __restrict__ C0, float* __restrict__ C1,
             const float* __restrict__ Cadd,
             int M, int N, int K, int nsplit)
{
    extern __shared__ char smem[];
    uint32_t sbase = smem_u32(smem);
    const int tid  = threadIdx.x;
    const int wid  = tid >> 5;
    const int lane = tid & 31;
    const int wm   = wid & 1;
    const int wn   = wid >> 1;
    const int bm   = blockIdx.y * BM;
    const int bn   = blockIdx.x * BN;
    const int NC   = K / BK;

    const __half* Ab = A + (size_t)bm * K;
    const __half* Bb = B + (size_t)bn * K;

    float acc[4][4][4];
#pragma unroll
    for (int i = 0; i < 4; i++)
#pragma unroll
        for (int j = 0; j < 4; j++)
#pragma unroll
            for (int q = 0; q < 4; q++) acc[i][j][q] = 0.0f;

    const int a_m  = wm * 64 + (lane & 15);
    const int a_ku = lane >> 4;
    const int b_n  = wn * 32 + (lane & 7) + ((lane >> 4) << 3);
    const int b_ku = (lane >> 3) & 1;

    issue_tile_loads(sbase, 0, Ab, Bb, 0,  K, tid); cp_commit();
    issue_tile_loads(sbase, 1, Ab, Bb, BK, K, tid); cp_commit();

    for (int c = 0; c < NC; c++) {
        if (c + 1 < NC) asm volatile("cp.async.wait_group 1;" ::: "memory");
        else            asm volatile("cp.async.wait_group 0;" ::: "memory");
        __syncthreads();

        if (c + 2 < NC) {
            issue_tile_loads(sbase, (c + 2) % NSTAGE, Ab, Bb, (c + 2) * BK, K, tid);
            cp_commit();
        }

        uint32_t stage = sbase + (uint32_t)(c % NSTAGE) * STAGE_BYTES;
#pragma unroll
        for (int ks = 0; ks < 4; ks++) {
            uint32_t a0[4], a1[4], a2[4], a3[4];
            uint32_t bb0[2], bb1[2], bb2[2], bb3[2];
#pragma unroll
            for (int mf = 0; mf < 4; mf++) {
                int m  = a_m + mf * 16;
                int ku = ks * 2 + a_ku;
                ldsm_x4(a0[mf], a1[mf], a2[mf], a3[mf],
                        stage + sw128((uint32_t)(m * 128 + ku * 16)));
            }
#pragma unroll
            for (int nf2 = 0; nf2 < 2; nf2++) {
                int n  = b_n + nf2 * 16;
                int ku = ks * 2 + b_ku;
                uint32_t r0, r1, r2, r3;
                ldsm_x4(r0, r1, r2, r3,
                        stage + OPB + sw128((uint32_t)(n * 128 + ku * 16)));
                if (nf2 == 0) { bb0[0] = r0; bb0[1] = r1; bb1[0] = r2; bb1[1] = r3; }
                else          { bb2[0] = r0; bb2[1] = r1; bb3[0] = r2; bb3[1] = r3; }
            }
#pragma unroll
            for (int mf = 0; mf < 4; mf++) {
                mma16(acc[mf][0][0], acc[mf][0][1], acc[mf][0][2], acc[mf][0][3],
                      a0[mf], a1[mf], a2[mf], a3[mf], bb0[0], bb0[1]);
                mma16(acc[mf][1][0], acc[mf][1][1], acc[mf][1][2], acc[mf][1][3],
                      a0[mf], a1[mf], a2[mf], a3[mf], bb1[0], bb1[1]);
                mma16(acc[mf][2][0], acc[mf][2][1], acc[mf][2][2], acc[mf][2][3],
                      a0[mf], a1[mf], a2[mf], a3[mf], bb2[0], bb2[1]);
                mma16(acc[mf][3][0], acc[mf][3][1], acc[mf][3][2], acc[mf][3][3],
                      a0[mf], a1[mf], a2[mf], a3[mf], bb3[0], bb3[1]);
            }
        }
        __syncthreads();
    }

    const int   inC0 = (bn < nsplit);
    float*      Cb   = inC0 ? C0 : C1;
    const int   ldc  = inC0 ? nsplit : (N - nsplit);
    const int   cb   = inC0 ? bn : bn - nsplit;

#pragma unroll
    for (int mf = 0; mf < 4; mf++) {
        int r0 = bm + wm * 64 + mf * 16 + (lane >> 2);
        int r1 = r0 + 8;
#pragma unroll
        for (int nf = 0; nf < 4; nf++) {
            int col = cb + wn * 32 + nf * 8 + (lane & 3) * 2;
            float2 v0 = make_float2(acc[mf][nf][0], acc[mf][nf][1]);
            float2 v1 = make_float2(acc[mf][nf][2], acc[mf][nf][3]);
            if (Cadd) {
                const float2 s0 = *(const float2*)(Cadd + (size_t)r0 * ldc + col);
                const float2 s1 = *(const float2*)(Cadd + (size_t)r1 * ldc + col);
                v0.x += s0.x; v0.y += s0.y;
                v1.x += s1.x; v1.y += s1.y;
            }
            *(float2*)(Cb + (size_t)r0 * ldc + col) = v0;
            *(float2*)(Cb + (size_t)r1 * ldc + col) = v1;
        }
    }
}

// ---------------------------------------------------------------------------
// Block-wide sum reduce
// ---------------------------------------------------------------------------
__device__ __forceinline__ float block_reduce_sum(float v) {
    __shared__ float sh[32];
    int lane = threadIdx.x & 31;
    int wid  = threadIdx.x >> 5;
#pragma unroll
    for (int o = 16; o; o >>= 1) v += __shfl_xor_sync(0xffffffffu, v, o);
    if (lane == 0) sh[wid] = v;
    __syncthreads();
    int nw = blockDim.x >> 5;
    if (wid == 0) {
        v = (lane < nw) ? sh[lane] : 0.0f;
#pragma unroll
        for (int o = 16; o; o >>= 1) v += __shfl_xor_sync(0xffffffffu, v, o);
    }
    return v;
}

// ---------------------------------------------------------------------------
// RMSNorm -> fp16. One block (256 thr) per row; W multiple of 1024.
// ---------------------------------------------------------------------------
__global__ void rmsnorm_f16_kernel(const float* __restrict__ in,
                                   __half* __restrict__ outp, int W) {
    int row = blockIdx.x;
    const float4* ir = (const float4*)(in + (size_t)row * W);
    int nvec = W >> 2;
    float ss = 0.0f;
    for (int i = threadIdx.x; i < nvec; i += 256) {
        float4 v = ir[i];
        ss += v.x * v.x + v.y * v.y + v.z * v.z + v.w * v.w;
    }
    ss = block_reduce_sum(ss);
    __shared__ float s_scale;
    if (threadIdx.x == 0) s_scale = rsqrtf(ss / (float)W + EPS_F);
    __syncthreads();
    float sc = s_scale;
    __half2* op = (__half2*)(outp + (size_t)row * W);
    for (int i = threadIdx.x; i < nvec; i += 256) {
        float4 v = ir[i];
        op[2 * i]     = __floats2half2_rn(v.x * sc, v.y * sc);
        op[2 * i + 1] = __floats2half2_rn(v.z * sc, v.w * sc);
    }
}

// ---------------------------------------------------------------------------
// Fused fp32 -> fp16 convert for W1, W2, W3 in one launch.
// ---------------------------------------------------------------------------
__global__ void wconv_all_kernel(const float* __restrict__ W1,
                                 const float* __restrict__ W2,
                                 const float* __restrict__ W3,
                                 __half* __restrict__ w12h,
                                 __half* __restrict__ w3h,
                                 int nv12, int nv3) {
    int i = blockIdx.x * blockDim.x + threadIdx.x;
    const float* src;
    __half2* dst;
    int j;
    if (i < nv12)                { src = W1; dst = (__half2*)w12h;                      j = i; }
    else if (i < 2 * nv12)       { src = W2; dst = (__half2*)(w12h + (size_t)nv12 * 4); j = i - nv12; }
    else if (i < 2 * nv12 + nv3) { src = W3; dst = (__half2*)w3h;                      j = i - 2 * nv12; }
    else return;
    float4 v = ((const float4*)src)[j];
    dst[2 * j]     = __floats2half2_rn(v.x, v.y);
    dst[2 * j + 1] = __floats2half2_rn(v.z, v.w);
}

// ---------------------------------------------------------------------------
// Chunked bar scan (parallel over T):
//   pass1: per (batch, chunk, channel) sum of exp over the chunk
//   pass2: exclusive prefix over chunks (per channel)
//   pass3: recompute exp within chunk from prefix; y'_t = sa_t * sb_t
// (1/t^2 cancels in the following rmsnorm; unstabilized — values bounded.)
// ---------------------------------------------------------------------------
__global__ void bar_pass1_kernel(const float* __restrict__ a,
                                 const float* __restrict__ b,
                                 float* __restrict__ pa,
                                 float* __restrict__ pb) {
    int h  = blockIdx.x * 256 + threadIdx.x;
    int c  = blockIdx.y;
    int bb = blockIdx.z;
    size_t base = (size_t)bb * SEQT * HID + (size_t)c * CHUNK * HID + h;
    const float* ap = a + base;
    const float* bp = b + base;
    float sa = 0.0f, sb = 0.0f;
#pragma unroll 4
    for (int t = 0; t < CHUNK; t++) {
        sa += __expf(ap[(size_t)t * HID]);
        sb += __expf(bp[(size_t)t * HID]);
    }
    int po = (bb * NCHUNK + c) * HID + h;
    pa[po] = sa;
    pb[po] = sb;
}

__global__ void bar_pass2_kernel(float* __restrict__ pa,
                                 float* __restrict__ pb) {
    int idx = blockIdx.x * 256 + threadIdx.x;   // 0 .. BATCH*HID-1
    int bb = idx >> 12;
    int h  = idx & (HID - 1);
    float runa = 0.0f, runb = 0.0f;
#pragma unroll
    for (int c = 0; c < NCHUNK; c++) {
        int off = (bb * NCHUNK + c) * HID + h;
        float va = pa[off], vb = pb[off];
        pa[off] = runa; pb[off] = runb;
        runa += va; runb += vb;
    }
}

__global__ void bar_pass3_kernel(const float* __restrict__ a,
                                 const float* __restrict__ b,
                                 const float* __restrict__ pa,
                                 const float* __restrict__ pb,
                                 float* __restrict__ y) {
    int h  = blockIdx.x * 256 + threadIdx.x;
    int c  = blockIdx.y;
    int bb = blockIdx.z;
    size_t base = (size_t)bb * SEQT * HID + (size_t)c * CHUNK * HID + h;
    const float* ap = a + base;
    const float* bp = b + base;
    float*       yp = y + base;
    int po = (bb * NCHUNK + c) * HID + h;
    float sa = pa[po], sb = pb[po];
#pragma unroll 4
    for (int t = 0; t < CHUNK; t++) {
        sa += __expf(ap[(size_t)t * HID]);
        sb += __expf(bp[(size_t)t * HID]);
        yp[(size_t)t * HID] = sa * sb;
    }
}

// ---------------------------------------------------------------------------
// kernel_launch
// ---------------------------------------------------------------------------
extern "C" void kernel_launch(void* const* d_in, const int* in_sizes, int n_in,
                              void* d_out, int out_size) {
    const float* x  = (const float*)d_in[0];
    const float* W1 = (const float*)d_in[1];
    const float* W2 = (const float*)d_in[2];
    const float* W3 = (const float*)d_in[3];
    float* out = (float*)d_out;

    __half *rh, *w12h, *w3h, *ynh;
    float *a_p, *b_p, *y_p, *pa_p, *pb_p;
    cudaGetSymbolAddress((void**)&rh,   g_rh);
    cudaGetSymbolAddress((void**)&w12h, g_w12h);
    cudaGetSymbolAddress((void**)&w3h,  g_w3h);
    cudaGetSymbolAddress((void**)&ynh,  g_ynh);
    cudaGetSymbolAddress((void**)&a_p,  g_a);
    cudaGetSymbolAddress((void**)&b_p,  g_b);
    cudaGetSymbolAddress((void**)&y_p,  g_y);
    cudaGetSymbolAddress((void**)&pa_p, g_pa);
    cudaGetSymbolAddress((void**)&pb_p, g_pb);

    cudaFuncSetAttribute(hgemm_kernel, cudaFuncAttributeMaxDynamicSharedMemorySize,
                         GEMM_SMEM);

    // Weight converts, one launch
    {
        int nv12 = (HID * EMB) / 4;
        int nv3  = (EMB * HID) / 4;
        int tot  = 2 * nv12 + nv3;
        wconv_all_kernel<<<(tot + 255) / 256, 256>>>(W1, W2, W3, w12h, w3h, nv12, nv3);
    }

    // 1) r = rmsnorm(x) -> fp16  [8192, 1024]
    rmsnorm_f16_kernel<<<MROWS, 256>>>(x, rh, EMB);

    // 2) fused: [a | b] = r @ [W1; W2]^T    M=8192, N=8192, K=1024
    hgemm_kernel<<<dim3((2 * HID) / BN, MROWS / BM), 256, GEMM_SMEM>>>(
        rh, w12h, a_p, b_p, nullptr, MROWS, 2 * HID, EMB, HID);

    // 3) y' = bar(a, b): chunked parallel scan
    {
        dim3 grid(HID / 256, NCHUNK, BATCH);
        bar_pass1_kernel<<<grid, 256>>>(a_p, b_p, pa_p, pb_p);
        bar_pass2_kernel<<<(BATCH * HID) / 256, 256>>>(pa_p, pb_p);
        bar_pass3_kernel<<<grid, 256>>>(a_p, b_p, pa_p, pb_p, y_p);
    }

    // 4) yn = rmsnorm(y') -> fp16  [8192, 4096]
    rmsnorm_f16_kernel<<<MROWS, 256>>>(y_p, ynh, HID);

    // 5) out = x + yn @ W3^T   M=8192, N=1024, K=4096
    hgemm_kernel<<<dim3(EMB / BN, MROWS / BM), 256, GEMM_SMEM>>>(
        ynh, w3h, out, out, x, MROWS, EMB, HID, EMB);
}

// round 12
// speedup vs baseline: 11.6996x; 1.1008x over previous
#include <cuda_runtime.h>
#include <cuda_bf16.h>
#include <cuda_fp16.h>
#include <cstdint>
#include <math.h>

// ---------------------------------------------------------------------------
// Problem constants
// ---------------------------------------------------------------------------
#define EMB   1024
#define HID   4096
#define BATCH 2
#define SEQT  4096
#define MROWS (BATCH * SEQT)   // 8192
#define EPS_F 1e-6f
#define NCHUNK 32
#define CHUNK  (SEQT / NCHUNK)   // 128  (== BM, tiles are chunk-aligned)

// ---------------------------------------------------------------------------
// Scratch buffers (static; runtime allocation forbidden)
// ---------------------------------------------------------------------------
__device__ __align__(16) __half g_rh  [(size_t)MROWS * EMB];          //  16 MB
__device__ __align__(16) __half g_w12h[(size_t)(2 * HID) * EMB];      //  16 MB
__device__ __align__(16) __half g_w3h [(size_t)EMB * HID];            //   8 MB
__device__ __align__(16) __half g_ynh [(size_t)MROWS * HID];          //  64 MB
__device__ __align__(16) __half g_ea  [(size_t)MROWS * HID];          //  64 MB exp(a)
__device__ __align__(16) __half g_eb  [(size_t)MROWS * HID];          //  64 MB exp(b)
__device__ __align__(16) __nv_bfloat16 g_y[(size_t)MROWS * HID];      //  64 MB
__device__ __align__(16) float g_pa[(size_t)BATCH * NCHUNK * HID];    //   1 MB
__device__ __align__(16) float g_pb[(size_t)BATCH * NCHUNK * HID];    //   1 MB

// ---------------------------------------------------------------------------
// PTX helpers (plain sm_103-legal)
// ---------------------------------------------------------------------------
__device__ __forceinline__ uint32_t smem_u32(const void* p) {
    uint32_t a;
    asm("{ .reg .u64 t; cvta.to.shared.u64 t, %1; cvt.u32.u64 %0, t; }"
        : "=r"(a) : "l"(p));
    return a;
}
__device__ __forceinline__ void cp16(uint32_t s, const void* g) {
    asm volatile("cp.async.cg.shared.global [%0], [%1], 16;" :: "r"(s), "l"(g));
}
__device__ __forceinline__ void cp_commit() {
    asm volatile("cp.async.commit_group;" ::: "memory");
}
__device__ __forceinline__ void ldsm_x4(uint32_t& r0, uint32_t& r1,
                                        uint32_t& r2, uint32_t& r3, uint32_t addr) {
    asm volatile("ldmatrix.sync.aligned.m8n8.x4.shared.b16 {%0,%1,%2,%3}, [%4];"
                 : "=r"(r0), "=r"(r1), "=r"(r2), "=r"(r3) : "r"(addr));
}
__device__ __forceinline__ void mma16(float& d0, float& d1, float& d2, float& d3,
                                      uint32_t a0, uint32_t a1, uint32_t a2, uint32_t a3,
                                      uint32_t b0, uint32_t b1) {
    asm volatile(
        "mma.sync.aligned.m16n8k16.row.col.f32.f16.f16.f32 "
        "{%0,%1,%2,%3}, {%4,%5,%6,%7}, {%8,%9}, {%0,%1,%2,%3};"
        : "+f"(d0), "+f"(d1), "+f"(d2), "+f"(d3)
        : "r"(a0), "r"(a1), "r"(a2), "r"(a3), "r"(b0), "r"(b1));
}

// ---------------------------------------------------------------------------
// fp16 NT GEMM (HMMA), 128x128x64 tiles, 3-stage cp.async, 256 thr, 2 CTA/SM.
// MODE 0: fp32 C (+ Cadd) with C0/C1 column split at nsplit.
// MODE 1: epilogue applies exp(), stores fp16 E0/E1, and reduces the tile's
//         128-row column sums into per-chunk partials pa/pb (chunk == M-tile).
// ---------------------------------------------------------------------------
#define BM 128
#define BN 128
#define BK 64
#define OPB 16384
#define STAGE_BYTES (2 * OPB)
#define NSTAGE 3
#define GEMM_SMEM (NSTAGE * STAGE_BYTES)

__device__ __forceinline__ uint32_t sw128(uint32_t off) {
    return off ^ ((off >> 3) & 0x70);
}

__device__ __forceinline__ void issue_tile_loads(
    uint32_t sbase, int st, const __half* Ab, const __half* Bb,
    int koff, int K, int tid)
{
    uint32_t stage = sbase + (uint32_t)st * STAGE_BYTES;
#pragma unroll
    for (int t = 0; t < 4; t++) {
        int idx = tid + t * 256;
        int row = idx >> 3;
        int u   = idx & 7;
        uint32_t sw = sw128((uint32_t)idx << 4);
        cp16(stage       + sw, Ab + (size_t)row * K + koff + u * 8);
        cp16(stage + OPB + sw, Bb + (size_t)row * K + koff + u * 8);
    }
}

template <int MODE>
__global__ void __launch_bounds__(256, 2)
hgemm_kernel(const __half* __restrict__ A, const __half* __restrict__ B,
             float* __restrict__ C0, float* __restrict__ C1,
             const float* __restrict__ Cadd,
             __half* __restrict__ E0, __half* __restrict__ E1,
             float* __restrict__ pa, float* __restrict__ pb,
             int M, int N, int K, int nsplit)
{
    extern __shared__ char smem[];
    uint32_t sbase = smem_u32(smem);
    const int tid  = threadIdx.x;
    const int wid  = tid >> 5;
    const int lane = tid & 31;
    const int wm   = wid & 1;
    const int wn   = wid >> 1;
    const int bm   = blockIdx.y * BM;
    const int bn   = blockIdx.x * BN;
    const int NC   = K / BK;

    const __half* Ab = A + (size_t)bm * K;
    const __half* Bb = B + (size_t)bn * K;

    float acc[4][4][4];
#pragma unroll
    for (int i = 0; i < 4; i++)
#pragma unroll
        for (int j = 0; j < 4; j++)
#pragma unroll
            for (int q = 0; q < 4; q++) acc[i][j][q] = 0.0f;

    const int a_m  = wm * 64 + (lane & 15);
    const int a_ku = lane >> 4;
    const int b_n  = wn * 32 + (lane & 7) + ((lane >> 4) << 3);
    const int b_ku = (lane >> 3) & 1;

    issue_tile_loads(sbase, 0, Ab, Bb, 0,  K, tid); cp_commit();
    issue_tile_loads(sbase, 1, Ab, Bb, BK, K, tid); cp_commit();

    for (int c = 0; c < NC; c++) {
        if (c + 1 < NC) asm volatile("cp.async.wait_group 1;" ::: "memory");
        else            asm volatile("cp.async.wait_group 0;" ::: "memory");
        __syncthreads();

        if (c + 2 < NC) {
            issue_tile_loads(sbase, (c + 2) % NSTAGE, Ab, Bb, (c + 2) * BK, K, tid);
            cp_commit();
        }

        uint32_t stage = sbase + (uint32_t)(c % NSTAGE) * STAGE_BYTES;
#pragma unroll
        for (int ks = 0; ks < 4; ks++) {
            uint32_t a0[4], a1[4], a2[4], a3[4];
            uint32_t bb0[2], bb1[2], bb2[2], bb3[2];
#pragma unroll
            for (int mf = 0; mf < 4; mf++) {
                int m  = a_m + mf * 16;
                int ku = ks * 2 + a_ku;
                ldsm_x4(a0[mf], a1[mf], a2[mf], a3[mf],
                        stage + sw128((uint32_t)(m * 128 + ku * 16)));
            }
#pragma unroll
            for (int nf2 = 0; nf2 < 2; nf2++) {
                int n  = b_n + nf2 * 16;
                int ku = ks * 2 + b_ku;
                uint32_t r0, r1, r2, r3;
                ldsm_x4(r0, r1, r2, r3,
                        stage + OPB + sw128((uint32_t)(n * 128 + ku * 16)));
                if (nf2 == 0) { bb0[0] = r0; bb0[1] = r1; bb1[0] = r2; bb1[1] = r3; }
                else          { bb2[0] = r0; bb2[1] = r1; bb3[0] = r2; bb3[1] = r3; }
            }
#pragma unroll
            for (int mf = 0; mf < 4; mf++) {
                mma16(acc[mf][0][0], acc[mf][0][1], acc[mf][0][2], acc[mf][0][3],
                      a0[mf], a1[mf], a2[mf], a3[mf], bb0[0], bb0[1]);
                mma16(acc[mf][1][0], acc[mf][1][1], acc[mf][1][2], acc[mf][1][3],
                      a0[mf], a1[mf], a2[mf], a3[mf], bb1[0], bb1[1]);
                mma16(acc[mf][2][0], acc[mf][2][1], acc[mf][2][2], acc[mf][2][3],
                      a0[mf], a1[mf], a2[mf], a3[mf], bb2[0], bb2[1]);
                mma16(acc[mf][3][0], acc[mf][3][1], acc[mf][3][2], acc[mf][3][3],
                      a0[mf], a1[mf], a2[mf], a3[mf], bb3[0], bb3[1]);
            }
        }
        __syncthreads();
    }

    const int inC0 = (bn < nsplit);
    const int ldc  = inC0 ? nsplit : (N - nsplit);
    const int cb   = inC0 ? bn : bn - nsplit;

    if (MODE == 0) {
        float* Cb = inC0 ? C0 : C1;
#pragma unroll
        for (int mf = 0; mf < 4; mf++) {
            int r0 = bm + wm * 64 + mf * 16 + (lane >> 2);
            int r1 = r0 + 8;
#pragma unroll
            for (int nf = 0; nf < 4; nf++) {
                int col = cb + wn * 32 + nf * 8 + (lane & 3) * 2;
                float2 v0 = make_float2(acc[mf][nf][0], acc[mf][nf][1]);
                float2 v1 = make_float2(acc[mf][nf][2], acc[mf][nf][3]);
                if (Cadd) {
                    const float2 s0 = *(const float2*)(Cadd + (size_t)r0 * ldc + col);
                    const float2 s1 = *(const float2*)(Cadd + (size_t)r1 * ldc + col);
                    v0.x += s0.x; v0.y += s0.y;
                    v1.x += s1.x; v1.y += s1.y;
                }
                *(float2*)(Cb + (size_t)r0 * ldc + col) = v0;
                *(float2*)(Cb + (size_t)r1 * ldc + col) = v1;
            }
        }
    } else {
        // exp in place
#pragma unroll
        for (int mf = 0; mf < 4; mf++)
#pragma unroll
            for (int nf = 0; nf < 4; nf++)
#pragma unroll
                for (int q = 0; q < 4; q++)
                    acc[mf][nf][q] = __expf(acc[mf][nf][q]);

        __half* Eb = inC0 ? E0 : E1;
#pragma unroll
        for (int mf = 0; mf < 4; mf++) {
            int r0 = bm + wm * 64 + mf * 16 + (lane >> 2);
            int r1 = r0 + 8;
#pragma unroll
            for (int nf = 0; nf < 4; nf++) {
                int col = cb + wn * 32 + nf * 8 + (lane & 3) * 2;
                *(__half2*)(Eb + (size_t)r0 * ldc + col) =
                    __floats2half2_rn(acc[mf][nf][0], acc[mf][nf][1]);
                *(__half2*)(Eb + (size_t)r1 * ldc + col) =
                    __floats2half2_rn(acc[mf][nf][2], acc[mf][nf][3]);
            }
        }

        // per-column sums over this tile's 128 rows -> chunk partials
        float cs[4][2];
#pragma unroll
        for (int nf = 0; nf < 4; nf++) {
            cs[nf][0] = cs[nf][1] = 0.0f;
#pragma unroll
            for (int mf = 0; mf < 4; mf++) {
                cs[nf][0] += acc[mf][nf][0] + acc[mf][nf][2];
                cs[nf][1] += acc[mf][nf][1] + acc[mf][nf][3];
            }
#pragma unroll
            for (int off = 4; off < 32; off <<= 1) {
                cs[nf][0] += __shfl_xor_sync(0xffffffffu, cs[nf][0], off);
                cs[nf][1] += __shfl_xor_sync(0xffffffffu, cs[nf][1], off);
            }
        }
        float* red = (float*)smem;   // stages dead after last mainloop sync
        if (lane < 4) {
#pragma unroll
            for (int nf = 0; nf < 4; nf++) {
                int col = wn * 32 + nf * 8 + lane * 2;
                red[wm * BN + col]     = cs[nf][0];
                red[wm * BN + col + 1] = cs[nf][1];
            }
        }
        __syncthreads();
        if (tid < BN) {
            int bb = bm / SEQT;
            int ch = (bm % SEQT) / CHUNK;
            float* P = inC0 ? pa : pb;
            P[(size_t)(bb * NCHUNK + ch) * HID + cb + tid] =
                red[tid] + red[BN + tid];
        }
    }
}

// ---------------------------------------------------------------------------
// Block-wide sum reduce
// ---------------------------------------------------------------------------
__device__ __forceinline__ float block_reduce_sum(float v) {
    __shared__ float sh[32];
    int lane = threadIdx.x & 31;
    int wid  = threadIdx.x >> 5;
#pragma unroll
    for (int o = 16; o; o >>= 1) v += __shfl_xor_sync(0xffffffffu, v, o);
    if (lane == 0) sh[wid] = v;
    __syncthreads();
    int nw = blockDim.x >> 5;
    if (wid == 0) {
        v = (lane < nw) ? sh[lane] : 0.0f;
#pragma unroll
        for (int o = 16; o; o >>= 1) v += __shfl_xor_sync(0xffffffffu, v, o);
    }
    return v;
}

// ---------------------------------------------------------------------------
// RMSNorm fp32 -> fp16. One block per row.
// ---------------------------------------------------------------------------
__global__ void rmsnorm_f16_kernel(const float* __restrict__ in,
                                   __half* __restrict__ outp, int W) {
    int row = blockIdx.x;
    const float4* ir = (const float4*)(in + (size_t)row * W);
    int nvec = W >> 2;
    float ss = 0.0f;
    for (int i = threadIdx.x; i < nvec; i += 256) {
        float4 v = ir[i];
        ss += v.x * v.x + v.y * v.y + v.z * v.z + v.w * v.w;
    }
    ss = block_reduce_sum(ss);
    __shared__ float s_scale;
    if (threadIdx.x == 0) s_scale = rsqrtf(ss / (float)W + EPS_F);
    __syncthreads();
    float sc = s_scale;
    __half2* op = (__half2*)(outp + (size_t)row * W);
    for (int i = threadIdx.x; i < nvec; i += 256) {
        float4 v = ir[i];
        op[2 * i]     = __floats2half2_rn(v.x * sc, v.y * sc);
        op[2 * i + 1] = __floats2half2_rn(v.z * sc, v.w * sc);
    }
}

// ---------------------------------------------------------------------------
// RMSNorm bf16 -> fp16. One block per row; W = HID.
// ---------------------------------------------------------------------------
__global__ void rmsnorm_bf16_f16_kernel(const __nv_bfloat16* __restrict__ in,
                                        __half* __restrict__ outp, int W) {
    int row = blockIdx.x;
    const uint2* ir = (const uint2*)(in + (size_t)row * W);   // 4 bf16 per uint2
    int nvec = W >> 2;
    float ss = 0.0f;
    for (int i = threadIdx.x; i < nvec; i += 256) {
        uint2 u = ir[i];
        __nv_bfloat162 p0 = *(__nv_bfloat162*)&u.x;
        __nv_bfloat162 p1 = *(__nv_bfloat162*)&u.y;
        float a0 = __bfloat162float(p0.x), a1 = __bfloat162float(p0.y);
        float a2 = __bfloat162float(p1.x), a3 = __bfloat162float(p1.y);
        ss += a0 * a0 + a1 * a1 + a2 * a2 + a3 * a3;
    }
    ss = block_reduce_sum(ss);
    __shared__ float s_scale;
    if (threadIdx.x == 0) s_scale = rsqrtf(ss / (float)W + EPS_F);
    __syncthreads();
    float sc = s_scale;
    __half2* op = (__half2*)(outp + (size_t)row * W);
    for (int i = threadIdx.x; i < nvec; i += 256) {
        uint2 u = ir[i];
        __nv_bfloat162 p0 = *(__nv_bfloat162*)&u.x;
        __nv_bfloat162 p1 = *(__nv_bfloat162*)&u.y;
        op[2 * i]     = __floats2half2_rn(__bfloat162float(p0.x) * sc,
                                          __bfloat162float(p0.y) * sc);
        op[2 * i + 1] = __floats2half2_rn(__bfloat162float(p1.x) * sc,
                                          __bfloat162float(p1.y) * sc);
    }
}

// ---------------------------------------------------------------------------
// Fused fp32 -> fp16 convert for W1, W2, W3 in one launch.
// ---------------------------------------------------------------------------
__global__ void wconv_all_kernel(const float* __restrict__ W1,
                                 const float* __restrict__ W2,
                                 const float* __restrict__ W3,
                                 __half* __restrict__ w12h,
                                 __half* __restrict__ w3h,
                                 int nv12, int nv3) {
    int i = blockIdx.x * blockDim.x + threadIdx.x;
    const float* src;
    __half2* dst;
    int j;
    if (i < nv12)                { src = W1; dst = (__half2*)w12h;                      j = i; }
    else if (i < 2 * nv12)       { src = W2; dst = (__half2*)(w12h + (size_t)nv12 * 4); j = i - nv12; }
    else if (i < 2 * nv12 + nv3) { src = W3; dst = (__half2*)w3h;                      j = i - 2 * nv12; }
    else return;
    float4 v = ((const float4*)src)[j];
    dst[2 * j]     = __floats2half2_rn(v.x, v.y);
    dst[2 * j + 1] = __floats2half2_rn(v.z, v.w);
}

// ---------------------------------------------------------------------------
// pass2: exclusive prefix over chunk sums (per channel)
// ---------------------------------------------------------------------------
__global__ void bar_pass2_kernel(float* __restrict__ pa,
                                 float* __restrict__ pb) {
    int idx = blockIdx.x * 256 + threadIdx.x;
    int bb = idx >> 12;
    int h  = idx & (HID - 1);
    float runa = 0.0f, runb = 0.0f;
#pragma unroll
    for (int c = 0; c < NCHUNK; c++) {
        int off = (bb * NCHUNK + c) * HID + h;
        float va = pa[off], vb = pb[off];
        pa[off] = runa; pb[off] = runb;
        runa += va; runb += vb;
    }
}

// ---------------------------------------------------------------------------
// pass3: within-chunk scan from prefix; reads fp16 ea/eb, writes bf16 y.
// Each thread handles 2 adjacent channels (half2 loads).
// ---------------------------------------------------------------------------
__global__ void bar_pass3_kernel(const __half* __restrict__ ea,
                                 const __half* __restrict__ eb,
                                 const float* __restrict__ pa,
                                 const float* __restrict__ pb,
                                 __nv_bfloat16* __restrict__ y) {
    int h2 = blockIdx.x * 256 + threadIdx.x;   // pair index, 0 .. HID/2-1
    int c  = blockIdx.y;
    int bb = blockIdx.z;
    size_t base = (size_t)bb * SEQT * HID + (size_t)c * CHUNK * HID + h2 * 2;
    const __half2* ap = (const __half2*)(ea + base);
    const __half2* bp = (const __half2*)(eb + base);
    __nv_bfloat162* yp = (__nv_bfloat162*)(y + base);

    int po = (bb * NCHUNK + c) * HID + h2 * 2;
    float sa0 = pa[po], sa1 = pa[po + 1];
    float sb0 = pb[po], sb1 = pb[po + 1];
#pragma unroll 4
    for (int t = 0; t < CHUNK; t++) {
        float2 va = __half22float2(ap[(size_t)t * (HID / 2)]);
        float2 vb = __half22float2(bp[(size_t)t * (HID / 2)]);
        sa0 += va.x; sa1 += va.y;
        sb0 += vb.x; sb1 += vb.y;
        yp[(size_t)t * (HID / 2)] = __floats2bfloat162_rn(sa0 * sb0, sa1 * sb1);
    }
}

// ---------------------------------------------------------------------------
// kernel_launch
// ---------------------------------------------------------------------------
extern "C" void kernel_launch(void* const* d_in, const int* in_sizes, int n_in,
                              void* d_out, int out_size) {
    const float* x  = (const float*)d_in[0];
    const float* W1 = (const float*)d_in[1];
    const float* W2 = (const float*)d_in[2];
    const float* W3 = (const float*)d_in[3];
    float* out = (float*)d_out;

    __half *rh, *w12h, *w3h, *ynh, *ea, *eb;
    __nv_bfloat16* y_p;
    float *pa_p, *pb_p;
    cudaGetSymbolAddress((void**)&rh,   g_rh);
    cudaGetSymbolAddress((void**)&w12h, g_w12h);
    cudaGetSymbolAddress((void**)&w3h,  g_w3h);
    cudaGetSymbolAddress((void**)&ynh,  g_ynh);
    cudaGetSymbolAddress((void**)&ea,   g_ea);
    cudaGetSymbolAddress((void**)&eb,   g_eb);
    cudaGetSymbolAddress((void**)&y_p,  g_y);
    cudaGetSymbolAddress((void**)&pa_p, g_pa);
    cudaGetSymbolAddress((void**)&pb_p, g_pb);

    cudaFuncSetAttribute(hgemm_kernel<0>, cudaFuncAttributeMaxDynamicSharedMemorySize,
                         GEMM_SMEM);
    cudaFuncSetAttribute(hgemm_kernel<1>, cudaFuncAttributeMaxDynamicSharedMemorySize,
                         GEMM_SMEM);

    // Weight converts, one launch
    {
        int nv12 = (HID * EMB) / 4;
        int nv3  = (EMB * HID) / 4;
        int tot  = 2 * nv12 + nv3;
        wconv_all_kernel<<<(tot + 255) / 256, 256>>>(W1, W2, W3, w12h, w3h, nv12, nv3);
    }

    // 1) r = rmsnorm(x) -> fp16
    rmsnorm_f16_kernel<<<MROWS, 256>>>(x, rh, EMB);

    // 2) fused GEMM1/2 + exp + chunk sums: ea,eb fp16 + pa,pb partial sums
    hgemm_kernel<1><<<dim3((2 * HID) / BN, MROWS / BM), 256, GEMM_SMEM>>>(
        rh, w12h, nullptr, nullptr, nullptr, ea, eb, pa_p, pb_p,
        MROWS, 2 * HID, EMB, HID);

    // 3) prefix over chunks, then within-chunk scan -> y bf16
    bar_pass2_kernel<<<(BATCH * HID) / 256, 256>>>(pa_p, pb_p);
    {
        dim3 grid(HID / 512, NCHUNK, BATCH);
        bar_pass3_kernel<<<grid, 256>>>(ea, eb, pa_p, pb_p, y_p);
    }

    // 4) yn = rmsnorm(y) -> fp16
    rmsnorm_bf16_f16_kernel<<<MROWS, 256>>>(y_p, ynh, HID);

    // 5) out = x + yn @ W3^T
    hgemm_kernel<0><<<dim3(EMB / BN, MROWS / BM), 256, GEMM_SMEM>>>(
        ynh, w3h, out, out, x, nullptr, nullptr, nullptr, nullptr,
        MROWS, EMB, HID, EMB);
}